// round 11
// baseline (speedup 1.0000x reference)
#include <cuda_runtime.h>
#include <math.h>

#define B 16384
#define T 32
#define S 16

#define READS_OFF 0
#define MEM_OFF   67108864
#define PTR_OFF   100663296
#define ACT_OFF   100925440

typedef unsigned long long u64;

__device__ float g_ZF[B * T * 128];
__device__ float g_VZ[B * T * 128];
__device__ float g_V0[B * S * 128];
__device__ float g_G0[B * S * S];
__device__ float g_P [B * T * S];
__device__ float g_H [128 * 128];
__device__ int   g_count;

__device__ __forceinline__ void fma2(u64& a, u64 w, u64 x) {
    asm("fma.rn.f32x2 %0, %1, %2, %0;" : "+l"(a) : "l"(w), "l"(x));
}
__device__ __forceinline__ u64 pack2(float x) {
    u64 r; asm("mov.b64 %0, {%1, %1};" : "=l"(r) : "f"(x)); return r;
}
__device__ __forceinline__ float hadd2(u64 a) {
    float lo, hi; asm("mov.b64 {%0, %1}, %2;" : "=f"(lo), "=f"(hi) : "l"(a));
    return lo + hi;
}
// M[e][a] for M = [[Wr, -Wi],[Wi, Wr]]
__device__ __forceinline__ float cmat(const float* Wr, const float* Wi, int e, int a) {
    if (e < 64) return (a < 64) ? Wr[e * 64 + a] : -Wi[e * 64 + (a - 64)];
    else        return (a < 64) ? Wi[(e - 64) * 64 + a] : Wr[(e - 64) * 64 + (a - 64)];
}

// ---------- H = Mq^T Mk ----------
__global__ void hprep_kernel(const float* __restrict__ Wqr, const float* __restrict__ Wqi,
                             const float* __restrict__ Wkr, const float* __restrict__ Wki) {
    int a = blockIdx.x, bb = threadIdx.x;
    float s = 0.f;
    for (int e = 0; e < 128; e++)
        s = fmaf(cmat(Wqr, Wqi, e, a), cmat(Wkr, Wki, e, bb), s);
    g_H[a * 128 + bb] = s;
    if (a == 0 && bb == 0) g_count = 0;
}

// ---------- phase1z: ZF = rope(z), VZ = Mv * ZF ----------
#define WST 68
#define Z_SMEM_BYTES ((2 * 64 * WST + 32 * 128 + 2048) * 4)
__global__ void __launch_bounds__(256) phase1z_kernel(
    const float* __restrict__ zr, const float* __restrict__ zi,
    const float* __restrict__ Wvr, const float* __restrict__ Wvi)
{
    extern __shared__ float sm[];
    float* sWr = sm;
    float* sWi = sm + 64 * WST;
    float* sX  = sm + 2 * 64 * WST;
    float* sCs = sX + 32 * 128;
    float* sSn = sCs + 1024;

    for (int k = threadIdx.x; k < 4096; k += 256) {
        int e = k >> 6, d = k & 63;
        sWr[d * WST + e] = Wvr[k];
        sWi[d * WST + e] = Wvi[k];
    }
    for (int k = threadIdx.x; k < 1024; k += 256) {
        int t = k >> 5, dm = k & 31;
        float ang = (float)t * exp2f(-0.41524101186092f * (float)dm);
        sincosf(ang, &sSn[k], &sCs[k]);
    }
    __syncthreads();

    const int lane = threadIdx.x & 31, warp = threadIdx.x >> 5;
    const int half = warp & 1;
    const int e4 = (lane & 15) * 4;
    const int r0 = ((warp >> 1) << 1) | (lane >> 4);

    for (int ch = blockIdx.x; ch < B * T / 32; ch += gridDim.x) {
        int rowbase = ch * 32;
        for (int k = threadIdx.x; k < 32 * 64; k += 256) {
            int i = k >> 6, d = k & 63;
            int row = rowbase + i;
            float a = zr[row * 64 + d], c = zi[row * 64 + d];
            int t = row & 31;
            float cs = sCs[t * 32 + (d & 31)], sn = sSn[t * 32 + (d & 31)];
            float xr = a * cs - c * sn, xi = a * sn + c * cs;
            sX[i * 128 + d] = xr; sX[i * 128 + 64 + d] = xi;
            g_ZF[row * 128 + d] = xr; g_ZF[row * 128 + 64 + d] = xi;
        }
        __syncthreads();

        u64 acc[4][2];
        #pragma unroll
        for (int q = 0; q < 4; q++) { acc[q][0] = 0ull; acc[q][1] = 0ull; }
        #pragma unroll 4
        for (int d = 0; d < 64; d++) {
            ulonglong2 wr2 = *(const ulonglong2*)(sWr + d * WST + e4);
            ulonglong2 wi2 = *(const ulonglong2*)(sWi + d * WST + e4);
            #pragma unroll
            for (int q = 0; q < 4; q++) {
                const float* x = sX + (r0 + q * 8) * 128;
                float xa = half ? x[64 + d] : x[d];
                float xb = half ? x[d]      : -x[64 + d];
                u64 pa = pack2(xa), pb = pack2(xb);
                fma2(acc[q][0], wr2.x, pa); fma2(acc[q][1], wr2.y, pa);
                fma2(acc[q][0], wi2.x, pb); fma2(acc[q][1], wi2.y, pb);
            }
        }
        int eo = e4 + half * 64;
        #pragma unroll
        for (int q = 0; q < 4; q++)
            *(ulonglong2*)(g_VZ + (rowbase + r0 + q * 8) * 128 + eo) =
                make_ulonglong2(acc[q][0], acc[q][1]);
        __syncthreads();
    }
}

// ---------- phase1m: per 4 batches: KT (smem only), V0, G0, P ----------
#define MST 132
#define M_SMEM_BYTES ((2 * 128 * MST + 64 * 128 + 64 * MST) * 4)
__global__ void __launch_bounds__(512) phase1m_kernel(
    const float* __restrict__ mem0,
    const float* __restrict__ Wvr, const float* __restrict__ Wvi)
{
    extern __shared__ float sm[];
    float* sH  = sm;                     // [128][MST] transposed H
    float* sMv = sm + 128 * MST;         // [128][MST] transposed Mv
    float* sX  = sm + 2 * 128 * MST;     // 64 x 128 (mem0 rows, then ZF rows)
    float* sKT = sX + 64 * 128;          // 64 x MST

    const int tid = threadIdx.x;
    for (int k = tid; k < 16384; k += 512) {
        int e = k >> 7, d = k & 127;
        sH[d * MST + e]  = g_H[k];
        sMv[d * MST + e] = cmat(Wvr, Wvi, e, d);
    }
    __syncthreads();

    const int lane = tid & 31, warp = tid >> 5;   // warp 0..15
    const int e4 = lane * 4;

    for (int g = blockIdx.x; g < B / 4; g += gridDim.x) {
        int bb0 = g * 4;
        for (int k = tid; k < 2048; k += 512)
            ((float4*)sX)[k] = ((const float4*)(mem0 + (size_t)bb0 * 2048))[k];
        __syncthreads();

        u64 kt[4][2], v[4][2];
        #pragma unroll
        for (int r = 0; r < 4; r++) { kt[r][0]=kt[r][1]=0ull; v[r][0]=v[r][1]=0ull; }
        #pragma unroll 2
        for (int d = 0; d < 128; d++) {
            ulonglong2 h2 = *(const ulonglong2*)(sH + d * MST + e4);
            ulonglong2 m2 = *(const ulonglong2*)(sMv + d * MST + e4);
            #pragma unroll
            for (int r = 0; r < 4; r++) {
                u64 px = pack2(sX[(warp * 4 + r) * 128 + d]);
                fma2(kt[r][0], h2.x, px); fma2(kt[r][1], h2.y, px);
                fma2(v[r][0],  m2.x, px); fma2(v[r][1],  m2.y, px);
            }
        }
        #pragma unroll
        for (int r = 0; r < 4; r++) {
            int row = warp * 4 + r;
            *(ulonglong2*)(sKT + row * MST + e4) = make_ulonglong2(kt[r][0], kt[r][1]);
            *(ulonglong2*)(g_V0 + (size_t)(bb0 * 16 + row) * 128 + e4) =
                make_ulonglong2(v[r][0], v[r][1]);
        }
        __syncthreads();

        // G0[bi][s][u] = mem0[s] . KT[u]
        for (int o = tid; o < 1024; o += 512) {
            int bi = o >> 8, s = (o >> 4) & 15, u = o & 15;
            const u64* xr = (const u64*)(sX  + (bi * 16 + s) * 128);
            const u64* kr = (const u64*)(sKT + (bi * 16 + u) * MST);
            u64 a = 0ull;
            #pragma unroll 8
            for (int e = 0; e < 64; e++) fma2(a, xr[e], kr[e]);
            g_G0[(size_t)(bb0 + bi) * 256 + s * 16 + u] = hadd2(a);
        }
        __syncthreads();

        // P[bi][t][u] = zf_t . KT[u] -- two passes of 2 batches, reuse sX
        for (int pair = 0; pair < 2; pair++) {
            int bz = bb0 + pair * 2;
            for (int k = tid; k < 2048; k += 512)
                ((float4*)sX)[k] = ((const float4*)(g_ZF + (size_t)bz * 32 * 128))[k];
            __syncthreads();
            int t = tid >> 4, u = tid & 15;
            #pragma unroll
            for (int bi = 0; bi < 2; bi++) {
                const u64* zrow = (const u64*)(sX  + (bi * 32 + t) * 128);
                const u64* kr   = (const u64*)(sKT + ((pair * 2 + bi) * 16 + u) * MST);
                u64 a = 0ull;
                #pragma unroll 8
                for (int e = 0; e < 64; e++) fma2(a, zrow[e], kr[e]);
                g_P[(size_t)(bz + bi) * 512 + t * 16 + u] = hadd2(a);
            }
            __syncthreads();
        }
    }
}

// ---------- phase2: 1 barrier/step, rotating compute warp ----------
__global__ void __launch_bounds__(128, 8) phase2_kernel(
    const float* __restrict__ ctrl, const float* __restrict__ mem0,
    const float* __restrict__ ptr0, float* __restrict__ out)
{
    const int b = blockIdx.x, j = threadIdx.x;
    const int lane = j & 31, wid = j >> 5;

    __shared__ float G0s[16][17];
    __shared__ float As[16][17];
    __shared__ float Ps[512];
    __shared__ float pushA[32], popA[32], stayA[32], betaA[32], cS[32];
    __shared__ float bSs[16], ptrS[16], nptrS[16];
    __shared__ float wSb[2][16];
    __shared__ float swS[2];

    float V0c[16];
    #pragma unroll
    for (int s = 0; s < 16; s++) V0c[s] = g_V0[(size_t)(b * 16 + s) * 128 + j];
    for (int k = j; k < 512; k += 128) Ps[k] = g_P[(size_t)b * 512 + k];
    {
        int s = j >> 3, u0 = (j & 7) * 2;
        G0s[s][u0]     = g_G0[(size_t)b * 256 + s * 16 + u0];
        G0s[s][u0 + 1] = g_G0[(size_t)b * 256 + s * 16 + u0 + 1];
    }
    if (j < 32) {
        int cb = (b * 32 + j) * 3;
        float g0 = 1.0f / (1.0f + __expf(-ctrl[cb]));
        float g1 = 1.0f / (1.0f + __expf(-ctrl[cb + 1]));
        float g2 = 1.0f / (1.0f + __expf(-ctrl[cb + 2]));
        float tot = g0 + g1 + g2 + 1e-6f;
        pushA[j] = g0 / tot; popA[j] = g1 / tot; stayA[j] = g2 / tot;
    }
    if (j < 16) { ptrS[j] = ptr0[b * 16 + j]; bSs[j] = 0.f; }
    __syncthreads();
    if (j == 0) {
        float bta = 1.f;
        for (int t = 0; t < 32; t++) { bta *= (1.f - pushA[t]); betaA[t] = bta; }
        float suf = 1.f;
        for (int t = 31; t >= 0; t--) { cS[t] = pushA[t] * suf; suf *= (1.f - pushA[t]); }
    }
    __syncthreads();

    float Rv = 0.f, vz_cur = 0.f;
    for (int i = 0; i < 33; i++) {
        float vz_nxt = 0.f;
        if (i < 32) vz_nxt = g_VZ[(size_t)(b * 32 + i) * 128 + j];

        if (i < 32 && wid == (i & 3) && lane < 16) {
            const int u = lane;
            float p = pushA[i];
            float bnew = fmaf(p, Ps[i * 16 + u] - bSs[u], bSs[u]);
            float np = p * ptrS[(u + 15) & 15] + popA[i] * ptrS[(u + 1) & 15]
                     + stayA[i] * ptrS[u];
            bSs[u] = bnew; nptrS[u] = np;
            __syncwarp(0x0000ffffu);
            float beta = betaA[i];
            float c2 = 0.125f * beta, c1 = c2 * beta;
            float l[16], mx = -1e30f;
            #pragma unroll
            for (int v = 0; v < 16; v++) {
                l[v] = fmaf(c1, G0s[u][v], c2 * bSs[v]);
                mx = fmaxf(mx, l[v]);
            }
            float sum = 0.f;
            #pragma unroll
            for (int v = 0; v < 16; v++) { l[v] = __expf(l[v] - mx); sum += l[v]; }
            float inv = 1.0f / sum;
            #pragma unroll
            for (int v = 0; v < 16; v++) As[u][v] = l[v] * inv;
            __syncwarp(0x0000ffffu);
            float w = 0.f;
            #pragma unroll
            for (int s2 = 0; s2 < 16; s2++) w = fmaf(nptrS[s2], As[s2][u], w);
            wSb[i & 1][u] = w;
            ptrS[u] = nptrS[u];
            float sw = w;
            sw += __shfl_xor_sync(0x0000ffffu, sw, 8);
            sw += __shfl_xor_sync(0x0000ffffu, sw, 4);
            sw += __shfl_xor_sync(0x0000ffffu, sw, 2);
            sw += __shfl_xor_sync(0x0000ffffu, sw, 1);
            if (u == 0) swS[i & 1] = sw;
        }

        if (i >= 1) {
            int t = i - 1;
            Rv = fmaf(pushA[t], vz_cur - Rv, Rv);
            float acc = 0.f;
            const float* wp = wSb[t & 1];
            #pragma unroll
            for (int u2 = 0; u2 < 16; u2++) acc = fmaf(wp[u2], V0c[u2], acc);
            out[READS_OFF + ((size_t)t * B + b) * 128 + j] = fmaf(betaA[t], acc, swS[t & 1] * Rv);
        }
        vz_cur = vz_nxt;
        __syncthreads();
    }

    // epilogue: mem_f = beta31*mem0 + Rm31 (Rm31 via suffix weights cS)
    float rm = 0.f;
    #pragma unroll 8
    for (int t = 0; t < 32; t++)
        rm = fmaf(cS[t], g_ZF[(size_t)(b * 32 + t) * 128 + j], rm);
    float bf = betaA[31];
    #pragma unroll
    for (int s = 0; s < 16; s++)
        out[MEM_OFF + (size_t)(b * 16 + s) * 128 + j] =
            fmaf(bf, mem0[(size_t)(b * 16 + s) * 128 + j], rm);
    if (j < 16) out[PTR_OFF + b * 16 + j] = ptrS[j];
    if (j < 32) {
        float pv = (j < 16) ? ptrS[j] : 0.f;
        unsigned m = __ballot_sync(0xffffffffu, pv > 0.1f);
        if (j == 0) atomicAdd(&g_count, __popc(m));
    }
}

__global__ void finalize_kernel(float* __restrict__ out) {
    out[ACT_OFF] = (float)g_count * (1.0f / (float)B);
}

extern "C" void kernel_launch(void* const* d_in, const int* in_sizes, int n_in,
                              void* d_out, int out_size) {
    const float* zr   = (const float*)d_in[0];
    const float* zi   = (const float*)d_in[1];
    const float* ctrl = (const float*)d_in[2];
    const float* mem0 = (const float*)d_in[3];
    const float* ptr0 = (const float*)d_in[4];
    const float* Wqr  = (const float*)d_in[5];
    const float* Wqi  = (const float*)d_in[6];
    const float* Wkr  = (const float*)d_in[7];
    const float* Wki  = (const float*)d_in[8];
    const float* Wvr  = (const float*)d_in[9];
    const float* Wvi  = (const float*)d_in[10];
    float* out = (float*)d_out;

    cudaFuncSetAttribute(phase1z_kernel, cudaFuncAttributeMaxDynamicSharedMemorySize, Z_SMEM_BYTES);
    cudaFuncSetAttribute(phase1m_kernel, cudaFuncAttributeMaxDynamicSharedMemorySize, M_SMEM_BYTES);

    hprep_kernel<<<128, 128>>>(Wqr, Wqi, Wkr, Wki);
    phase1z_kernel<<<444, 256, Z_SMEM_BYTES>>>(zr, zi, Wvr, Wvi);
    phase1m_kernel<<<148, 512, M_SMEM_BYTES>>>(mem0, Wvr, Wvi);
    phase2_kernel<<<B, 128>>>(ctrl, mem0, ptr0, out);
    finalize_kernel<<<1, 1>>>(out);
}

// round 12
// speedup vs baseline: 1.3161x; 1.3161x over previous
#include <cuda_runtime.h>
#include <math.h>

#define B 16384
#define T 32
#define S 16

#define READS_OFF 0
#define MEM_OFF   67108864
#define PTR_OFF   100663296
#define ACT_OFF   100925440

__device__ float g_ZF[B * T * 128];
__device__ float g_VZ[B * T * 128];
__device__ float g_V0[B * S * 128];
__device__ float g_G0[B * S * S];
__device__ float g_P [B * T * S];
__device__ float g_W [B * T * S];
__device__ float g_AUX[B * 128];     // per batch: push[32], beta[32], cS[32], sw[32]
__device__ float g_H [128 * 128];
__device__ int   g_count;

__device__ __forceinline__ void fma4(float4& a, const float4 w, const float s) {
    a.x = fmaf(w.x, s, a.x); a.y = fmaf(w.y, s, a.y);
    a.z = fmaf(w.z, s, a.z); a.w = fmaf(w.w, s, a.w);
}
__device__ __forceinline__ void fma4n(float4& a, const float4 w, const float s) {
    a.x = fmaf(w.x, -s, a.x); a.y = fmaf(w.y, -s, a.y);
    a.z = fmaf(w.z, -s, a.z); a.w = fmaf(w.w, -s, a.w);
}
// M[e][a] for M = [[Wr, -Wi],[Wi, Wr]]
__device__ __forceinline__ float cmat(const float* Wr, const float* Wi, int e, int a) {
    if (e < 64) return (a < 64) ? Wr[e * 64 + a] : -Wi[e * 64 + (a - 64)];
    else        return (a < 64) ? Wi[(e - 64) * 64 + a] : Wr[(e - 64) * 64 + (a - 64)];
}

// ---------- H = Mq^T Mk ----------
__global__ void hprep_kernel(const float* __restrict__ Wqr, const float* __restrict__ Wqi,
                             const float* __restrict__ Wkr, const float* __restrict__ Wki) {
    int a = blockIdx.x, bb = threadIdx.x;
    float s = 0.f;
    for (int e = 0; e < 128; e++)
        s = fmaf(cmat(Wqr, Wqi, e, a), cmat(Wkr, Wki, e, bb), s);
    g_H[a * 128 + bb] = s;
    if (a == 0 && bb == 0) g_count = 0;
}

// ---------- phase1z: ZF = rope(z), VZ = Mv * ZF  (R8 known-good) ----------
#define WST 68
#define Z_SMEM_BYTES ((2 * 64 * WST + 32 * 128 + 2048) * 4)
__global__ void __launch_bounds__(256) phase1z_kernel(
    const float* __restrict__ zr, const float* __restrict__ zi,
    const float* __restrict__ Wvr, const float* __restrict__ Wvi)
{
    extern __shared__ float sm[];
    float* sWr = sm;
    float* sWi = sm + 64 * WST;
    float* sX  = sm + 2 * 64 * WST;
    float* sCs = sX + 32 * 128;
    float* sSn = sCs + 1024;

    for (int k = threadIdx.x; k < 4096; k += 256) {
        int e = k >> 6, d = k & 63;
        sWr[d * WST + e] = Wvr[k];
        sWi[d * WST + e] = Wvi[k];
    }
    for (int k = threadIdx.x; k < 1024; k += 256) {
        int t = k >> 5, dm = k & 31;
        float ang = (float)t * exp2f(-0.41524101186092f * (float)dm);
        sincosf(ang, &sSn[k], &sCs[k]);
    }
    __syncthreads();

    const int lane = threadIdx.x & 31, warp = threadIdx.x >> 5;
    const int half = warp & 1;
    const int e4 = (lane & 15) * 4;
    const int r0 = ((warp >> 1) << 1) | (lane >> 4);

    for (int ch = blockIdx.x; ch < B * T / 32; ch += gridDim.x) {
        int rowbase = ch * 32;
        for (int k = threadIdx.x; k < 32 * 64; k += 256) {
            int i = k >> 6, d = k & 63;
            int row = rowbase + i;
            float a = zr[row * 64 + d], c = zi[row * 64 + d];
            int t = row & 31;
            float cs = sCs[t * 32 + (d & 31)], sn = sSn[t * 32 + (d & 31)];
            float xr = a * cs - c * sn, xi = a * sn + c * cs;
            sX[i * 128 + d] = xr; sX[i * 128 + 64 + d] = xi;
            g_ZF[row * 128 + d] = xr; g_ZF[row * 128 + 64 + d] = xi;
        }
        __syncthreads();

        float4 acc[4];
        #pragma unroll
        for (int q = 0; q < 4; q++) acc[q] = make_float4(0.f, 0.f, 0.f, 0.f);
        #pragma unroll 4
        for (int d = 0; d < 64; d++) {
            float4 wr = *(const float4*)(sWr + d * WST + e4);
            float4 wi = *(const float4*)(sWi + d * WST + e4);
            #pragma unroll
            for (int q = 0; q < 4; q++) {
                const float* x = sX + (r0 + q * 8) * 128;
                float xa = half ? x[64 + d] : x[d];
                float xb = half ? x[d]      : x[64 + d];
                fma4(acc[q], wr, xa);
                if (half) fma4(acc[q], wi, xb); else fma4n(acc[q], wi, xb);
            }
        }
        int eo = e4 + half * 64;
        #pragma unroll
        for (int q = 0; q < 4; q++)
            *(float4*)(g_VZ + (rowbase + r0 + q * 8) * 128 + eo) = acc[q];
        __syncthreads();
    }
}

// ---------- phase1m: per batch: KT (smem), V0, G0, P ----------
#define MST 132
#define M_SMEM_BYTES ((2 * 128 * MST + 4096 + 16 * MST) * 4)
__global__ void __launch_bounds__(256) phase1m_kernel(
    const float* __restrict__ mem0,
    const float* __restrict__ Wvr, const float* __restrict__ Wvi)
{
    extern __shared__ float sm[];
    float* sH  = sm;                     // [128][MST] transposed H
    float* sMv = sm + 128 * MST;
    float* sX  = sm + 2 * 128 * MST;     // 4096 floats (mem0 16x128, later ZF 32x128)
    float* sKT = sX + 4096;              // 16 x MST

    for (int k = threadIdx.x; k < 16384; k += 256) {
        int e = k >> 7, d = k & 127;
        sH[d * MST + e]  = g_H[k];
        sMv[d * MST + e] = cmat(Wvr, Wvi, e, d);
    }
    __syncthreads();

    const int lane = threadIdx.x & 31, warp = threadIdx.x >> 5;
    const int e4 = lane * 4;
    const int r0 = warp * 2;

    for (int bb = blockIdx.x; bb < B; bb += gridDim.x) {
        for (int k = threadIdx.x; k < 512; k += 256)
            ((float4*)sX)[k] = ((const float4*)(mem0 + (size_t)bb * 2048))[k];
        __syncthreads();

        float4 kt0 = {0.f,0.f,0.f,0.f}, kt1 = kt0, v0 = kt0, v1 = kt0;
        #pragma unroll 4
        for (int d = 0; d < 128; d++) {
            float4 h4 = *(const float4*)(sH + d * MST + e4);
            float4 m4 = *(const float4*)(sMv + d * MST + e4);
            float x0 = sX[r0 * 128 + d], x1 = sX[(r0 + 1) * 128 + d];
            fma4(kt0, h4, x0); fma4(v0, m4, x0);
            fma4(kt1, h4, x1); fma4(v1, m4, x1);
        }
        size_t gb = (size_t)(bb * 16 + r0) * 128 + e4;
        *(float4*)(g_V0 + gb) = v0;
        *(float4*)(g_V0 + gb + 128) = v1;
        *(float4*)(sKT + r0 * MST + e4) = kt0;
        *(float4*)(sKT + (r0 + 1) * MST + e4) = kt1;
        __syncthreads();

        {   // G0[s][u] = mem0[s] . KT[u]
            int s = threadIdx.x >> 4, u = threadIdx.x & 15;
            float a = 0.f;
            #pragma unroll 4
            for (int e = 0; e < 128; e++)
                a = fmaf(sX[s * 128 + e], sKT[u * MST + e], a);
            g_G0[(size_t)bb * 256 + threadIdx.x] = a;
        }
        __syncthreads();

        // load ZF rows (overwrite sX), then P[t][u] = zf_t . KT[u]
        for (int k = threadIdx.x; k < 1024; k += 256)
            ((float4*)sX)[k] = ((const float4*)(g_ZF + (size_t)bb * 4096))[k];
        __syncthreads();
        for (int o = threadIdx.x; o < 512; o += 256) {
            int t = o >> 4, u = o & 15;
            float a = 0.f;
            #pragma unroll 4
            for (int e = 0; e < 128; e++)
                a = fmaf(sX[t * 128 + e], sKT[u * MST + e], a);
            g_P[(size_t)bb * 512 + o] = a;
        }
        __syncthreads();
    }
}

// ---------- K1: per-batch serial chain, warp handles 2 batches ----------
__global__ void __launch_bounds__(256) k1_kernel(
    const float* __restrict__ ctrl, const float* __restrict__ ptr0,
    float* __restrict__ out)
{
    __shared__ float sG0[16][16 * 17];
    __shared__ float sAs[16][16 * 17];
    __shared__ float sP [16][512];
    __shared__ float sg [16][3][32];
    __shared__ float sbeta[16][32];
    __shared__ float scs[16][32];
    __shared__ float ssw[16][32];
    __shared__ float sb [16][16];
    __shared__ float snp[16][16];
    __shared__ float sptr[16][16];

    const int lane = threadIdx.x & 31, warp = threadIdx.x >> 5;
    const int half = lane >> 4, u = lane & 15;
    const int slot = warp * 2 + half;
    const int bb = blockIdx.x * 16 + slot;

    // init: gates (2 steps per lane), G0, P, ptr, b
    #pragma unroll
    for (int st = u; st < 32; st += 16) {
        int cb = (bb * 32 + st) * 3;
        float g0 = 1.0f / (1.0f + __expf(-ctrl[cb]));
        float g1 = 1.0f / (1.0f + __expf(-ctrl[cb + 1]));
        float g2 = 1.0f / (1.0f + __expf(-ctrl[cb + 2]));
        float tot = g0 + g1 + g2 + 1e-6f;
        sg[slot][0][st] = g0 / tot;
        sg[slot][1][st] = g1 / tot;
        sg[slot][2][st] = g2 / tot;
    }
    #pragma unroll
    for (int v = 0; v < 16; v++)
        sG0[slot][u * 17 + v] = g_G0[(size_t)bb * 256 + u * 16 + v];
    for (int k = u; k < 512; k += 16)
        sP[slot][k] = g_P[(size_t)bb * 512 + k];
    sptr[slot][u] = ptr0[bb * 16 + u];
    sb[slot][u] = 0.f;
    __syncwarp();
    if (u == 0) {
        float bta = 1.f;
        for (int t = 0; t < 32; t++) { bta *= (1.f - sg[slot][0][t]); sbeta[slot][t] = bta; }
        float suf = 1.f;
        for (int t = 31; t >= 0; t--) {
            scs[slot][t] = sg[slot][0][t] * suf;
            suf *= (1.f - sg[slot][0][t]);
        }
    }
    __syncwarp();

    for (int t = 0; t < 32; t++) {
        float p = sg[slot][0][t], po = sg[slot][1][t], st = sg[slot][2][t];
        float bu = sb[slot][u];
        bu = fmaf(p, sP[slot][t * 16 + u] - bu, bu);
        float np = p * sptr[slot][(u + 15) & 15] + po * sptr[slot][(u + 1) & 15]
                 + st * sptr[slot][u];
        sb[slot][u] = bu; snp[slot][u] = np;
        __syncwarp();

        float beta = sbeta[slot][t];
        float c2 = 0.125f * beta, c1 = c2 * beta;
        float l[16], mx = -1e30f;
        #pragma unroll
        for (int v = 0; v < 16; v++) {
            l[v] = fmaf(c1, sG0[slot][u * 17 + v], c2 * sb[slot][v]);
            mx = fmaxf(mx, l[v]);
        }
        float sum = 0.f;
        #pragma unroll
        for (int v = 0; v < 16; v++) { l[v] = __expf(l[v] - mx); sum += l[v]; }
        float inv = 1.0f / sum;
        #pragma unroll
        for (int v = 0; v < 16; v++) sAs[slot][u * 17 + v] = l[v] * inv;
        __syncwarp();

        float w = 0.f;
        #pragma unroll
        for (int s2 = 0; s2 < 16; s2++)
            w = fmaf(snp[slot][s2], sAs[slot][s2 * 17 + u], w);
        g_W[(size_t)bb * 512 + t * 16 + u] = w;
        sptr[slot][u] = np;
        float sw = w;
        sw += __shfl_xor_sync(0xffffffffu, sw, 8, 16);
        sw += __shfl_xor_sync(0xffffffffu, sw, 4, 16);
        sw += __shfl_xor_sync(0xffffffffu, sw, 2, 16);
        sw += __shfl_xor_sync(0xffffffffu, sw, 1, 16);
        if (u == 0) ssw[slot][t] = sw;
        __syncwarp();
    }

    // flush aux (coalesced-ish), ptr_f, count
    for (int k = u; k < 32; k += 16) {
        g_AUX[(size_t)bb * 128 + k]      = sg[slot][0][k];
        g_AUX[(size_t)bb * 128 + 32 + k] = sbeta[slot][k];
        g_AUX[(size_t)bb * 128 + 64 + k] = scs[slot][k];
        g_AUX[(size_t)bb * 128 + 96 + k] = ssw[slot][k];
    }
    out[PTR_OFF + bb * 16 + u] = sptr[slot][u];
    unsigned m = __ballot_sync(0xffffffffu, sptr[slot][u] > 0.1f);
    if (lane == 0) atomicAdd(&g_count, __popc(m));
}

// ---------- K2: barrier-free streaming output ----------
__global__ void __launch_bounds__(128) k2_kernel(
    const float* __restrict__ mem0, float* __restrict__ out)
{
    const int b = blockIdx.x, j = threadIdx.x;
    __shared__ float w2[512];
    __shared__ float aux2[128];

    ((float4*)w2)[j] = ((const float4*)(g_W + (size_t)b * 512))[j];
    aux2[j] = g_AUX[(size_t)b * 128 + j];
    float V0c[16];
    #pragma unroll
    for (int s = 0; s < 16; s++) V0c[s] = g_V0[(size_t)(b * 16 + s) * 128 + j];
    __syncthreads();

    const float* pushA = aux2;
    const float* betaA = aux2 + 32;
    const float* csA   = aux2 + 64;
    const float* swA   = aux2 + 96;

    float Rv = 0.f;
    float vz = g_VZ[(size_t)(b * 32) * 128 + j];
    #pragma unroll 4
    for (int t = 0; t < 32; t++) {
        float vzn = (t < 31) ? g_VZ[(size_t)(b * 32 + t + 1) * 128 + j] : 0.f;
        Rv = fmaf(pushA[t], vz - Rv, Rv);
        float acc = 0.f;
        const float* wp = w2 + t * 16;
        #pragma unroll
        for (int u2 = 0; u2 < 16; u2++) acc = fmaf(wp[u2], V0c[u2], acc);
        out[READS_OFF + ((size_t)t * B + b) * 128 + j] = fmaf(betaA[t], acc, swA[t] * Rv);
        vz = vzn;
    }

    float rm = 0.f;
    #pragma unroll 8
    for (int t = 0; t < 32; t++)
        rm = fmaf(csA[t], g_ZF[(size_t)(b * 32 + t) * 128 + j], rm);
    float bf = betaA[31];
    #pragma unroll
    for (int s = 0; s < 16; s++)
        out[MEM_OFF + (size_t)(b * 16 + s) * 128 + j] =
            fmaf(bf, mem0[(size_t)(b * 16 + s) * 128 + j], rm);
}

__global__ void finalize_kernel(float* __restrict__ out) {
    out[ACT_OFF] = (float)g_count * (1.0f / (float)B);
}

extern "C" void kernel_launch(void* const* d_in, const int* in_sizes, int n_in,
                              void* d_out, int out_size) {
    const float* zr   = (const float*)d_in[0];
    const float* zi   = (const float*)d_in[1];
    const float* ctrl = (const float*)d_in[2];
    const float* mem0 = (const float*)d_in[3];
    const float* ptr0 = (const float*)d_in[4];
    const float* Wqr  = (const float*)d_in[5];
    const float* Wqi  = (const float*)d_in[6];
    const float* Wkr  = (const float*)d_in[7];
    const float* Wki  = (const float*)d_in[8];
    const float* Wvr  = (const float*)d_in[9];
    const float* Wvi  = (const float*)d_in[10];
    float* out = (float*)d_out;

    cudaFuncSetAttribute(phase1z_kernel, cudaFuncAttributeMaxDynamicSharedMemorySize, Z_SMEM_BYTES);
    cudaFuncSetAttribute(phase1m_kernel, cudaFuncAttributeMaxDynamicSharedMemorySize, M_SMEM_BYTES);

    hprep_kernel<<<128, 128>>>(Wqr, Wqi, Wkr, Wki);
    phase1z_kernel<<<444, 256, Z_SMEM_BYTES>>>(zr, zi, Wvr, Wvi);
    phase1m_kernel<<<148, 256, M_SMEM_BYTES>>>(mem0, Wvr, Wvi);
    k1_kernel<<<B / 16, 256>>>(ctrl, ptr0, out);
    k2_kernel<<<B, 128>>>(mem0, out);
    finalize_kernel<<<1, 1>>>(out);
}

// round 13
// speedup vs baseline: 2.6273x; 1.9962x over previous
#include <cuda_runtime.h>
#include <math.h>

#define B 16384
#define T 32
#define S 16

#define READS_OFF 0
#define MEM_OFF   67108864
#define PTR_OFF   100663296
#define ACT_OFF   100925440

__device__ float g_VZ[B * T * 128];
__device__ float g_KT[B * S * 128];
__device__ float g_V0[B * S * 128];
__device__ float g_G0[B * S * S];
__device__ float g_P [B * T * S];
__device__ float g_W [B * T * S];
__device__ float g_AUX[B * 128];     // push[32], beta[32], cS[32], sw[32]
__device__ float g_H [128 * 128];
__device__ float g_Mv[128 * 128];
__device__ int   g_count;

__device__ __forceinline__ unsigned f2tf(float x) {
    unsigned r; asm("cvt.rna.tf32.f32 %0, %1;" : "=r"(r) : "f"(x)); return r;
}
__device__ __forceinline__ void mma8(float4& c, const uint4 a, const uint2 b) {
    asm("mma.sync.aligned.m16n8k8.row.col.f32.tf32.tf32.f32 "
        "{%0,%1,%2,%3}, {%4,%5,%6,%7}, {%8,%9}, {%0,%1,%2,%3};"
        : "+f"(c.x), "+f"(c.y), "+f"(c.z), "+f"(c.w)
        : "r"(a.x), "r"(a.y), "r"(a.z), "r"(a.w), "r"(b.x), "r"(b.y));
}
// M[e][a] for M = [[Wr, -Wi],[Wi, Wr]]
__device__ __forceinline__ float cmat(const float* Wr, const float* Wi, int e, int a) {
    if (e < 64) return (a < 64) ? Wr[e * 64 + a] : -Wi[e * 64 + (a - 64)];
    else        return (a < 64) ? Wi[(e - 64) * 64 + a] : Wr[(e - 64) * 64 + (a - 64)];
}

// ---------- hprep: H = Mq^T Mk, Mv expanded ----------
__global__ void hprep_kernel(const float* __restrict__ Wqr, const float* __restrict__ Wqi,
                             const float* __restrict__ Wkr, const float* __restrict__ Wki,
                             const float* __restrict__ Wvr, const float* __restrict__ Wvi) {
    int a = blockIdx.x, bb = threadIdx.x;
    float s = 0.f;
    for (int e = 0; e < 128; e++)
        s = fmaf(cmat(Wqr, Wqi, e, a), cmat(Wkr, Wki, e, bb), s);
    g_H[a * 128 + bb] = s;
    g_Mv[a * 128 + bb] = cmat(Wvr, Wvi, a, bb);
    if (a == 0 && bb == 0) g_count = 0;
}

// ---------- phase1z: VZ = rope(z) @ Mv^T  (tf32 mma) ----------
// smem: XA uint4[4][16][32] (32KB) | WB uint2[16][16][32] (64KB) | cs,sn (8KB)
#define Z_SMEM_BYTES (32768 + 65536 + 8192)
__global__ void __launch_bounds__(128, 2) phase1z_kernel(
    const float* __restrict__ zr, const float* __restrict__ zi)
{
    extern __shared__ char smz[];
    uint4* XA  = (uint4*)smz;
    uint2* WB  = (uint2*)(smz + 32768);
    float* sCs = (float*)(smz + 98304);
    float* sSn = sCs + 1024;
    const int tid = threadIdx.x;
    const int ln = tid & 31, w = tid >> 5;
    const int g = ln >> 2, c = ln & 3;

    for (int fl = tid; fl < 8192; fl += 128) {
        int l2 = fl & 31, nt = (fl >> 5) & 15, kt = fl >> 9;
        int g2 = l2 >> 2, c2 = l2 & 3;
        int n = nt * 8 + g2, k = kt * 8 + c2;
        WB[(kt * 16 + nt) * 32 + l2] =
            make_uint2(f2tf(g_Mv[n * 128 + k]), f2tf(g_Mv[n * 128 + k + 4]));
    }
    for (int k = tid; k < 1024; k += 128) {
        int t = k >> 5, dm = k & 31;
        float ang = (float)t * exp2f(-0.41524101186092f * (float)dm);
        sincosf(ang, &sSn[k], &sCs[k]);
    }
    __syncthreads();

    for (int ch = blockIdx.x; ch < (B * T) / 64; ch += gridDim.x) {
        int rowbase = ch * 64;
        for (int fl = tid; fl < 1024; fl += 128) {
            int l2 = fl & 31, kt = (fl >> 5) & 7, rt = fl >> 8;
            int g2 = l2 >> 2, c2 = l2 & 3;
            int r1 = rt * 16 + g2, r2 = r1 + 8;
            int d1 = kt * 8 + c2, d2 = d1 + 4;
            int row1 = rowbase + r1, row2 = rowbase + r2;
            float z11 = zr[row1 * 64 + d1], y11 = zi[row1 * 64 + d1];
            float z12 = zr[row1 * 64 + d2], y12 = zi[row1 * 64 + d2];
            float z21 = zr[row2 * 64 + d1], y21 = zi[row2 * 64 + d1];
            float z22 = zr[row2 * 64 + d2], y22 = zi[row2 * 64 + d2];
            int t1 = row1 & 31, t2 = row2 & 31;
            float cA = sCs[t1 * 32 + (d1 & 31)], sA = sSn[t1 * 32 + (d1 & 31)];
            float cBv = sCs[t1 * 32 + (d2 & 31)], sB = sSn[t1 * 32 + (d2 & 31)];
            float cC = sCs[t2 * 32 + (d1 & 31)], sC = sSn[t2 * 32 + (d1 & 31)];
            float cD = sCs[t2 * 32 + (d2 & 31)], sD = sSn[t2 * 32 + (d2 & 31)];
            float xr11 = z11 * cA - y11 * sA, xi11 = z11 * sA + y11 * cA;
            float xr12 = z12 * cBv - y12 * sB, xi12 = z12 * sB + y12 * cBv;
            float xr21 = z21 * cC - y21 * sC, xi21 = z21 * sC + y21 * cC;
            float xr22 = z22 * cD - y22 * sD, xi22 = z22 * sD + y22 * cD;
            XA[(rt * 16 + kt) * 32 + l2] =
                make_uint4(f2tf(xr11), f2tf(xr21), f2tf(xr12), f2tf(xr22));
            XA[(rt * 16 + kt + 8) * 32 + l2] =
                make_uint4(f2tf(xi11), f2tf(xi21), f2tf(xi12), f2tf(xi22));
        }
        __syncthreads();

        float4 C[16];
        #pragma unroll
        for (int nt = 0; nt < 16; nt++) C[nt] = make_float4(0.f, 0.f, 0.f, 0.f);
        #pragma unroll
        for (int kt = 0; kt < 16; kt++) {
            uint4 a = XA[(w * 16 + kt) * 32 + ln];
            #pragma unroll
            for (int nt = 0; nt < 16; nt++)
                mma8(C[nt], a, WB[(kt * 16 + nt) * 32 + ln]);
        }
        int row = rowbase + w * 16 + g;
        #pragma unroll
        for (int nt = 0; nt < 16; nt++) {
            *(float2*)(g_VZ + (size_t)row * 128 + nt * 8 + 2 * c) = make_float2(C[nt].x, C[nt].y);
            *(float2*)(g_VZ + (size_t)(row + 8) * 128 + nt * 8 + 2 * c) = make_float2(C[nt].z, C[nt].w);
        }
        __syncthreads();
    }
}

// ---------- generic tf32 GEMM: OUT[m][n] = sum_k X[m][k] * Wm[n][k], M rows ----------
#define G_SMEM_BYTES (32768 + 65536)
__global__ void __launch_bounds__(128, 2) gemm_kernel(
    const float* __restrict__ X, const float* __restrict__ Wm,
    float* __restrict__ OUT, int nrows)
{
    extern __shared__ char smg[];
    uint4* XA = (uint4*)smg;
    uint2* WB = (uint2*)(smg + 32768);
    const int tid = threadIdx.x;
    const int ln = tid & 31, w = tid >> 5;
    const int g = ln >> 2, c = ln & 3;

    for (int fl = tid; fl < 8192; fl += 128) {
        int l2 = fl & 31, nt = (fl >> 5) & 15, kt = fl >> 9;
        int g2 = l2 >> 2, c2 = l2 & 3;
        int n = nt * 8 + g2, k = kt * 8 + c2;
        WB[(kt * 16 + nt) * 32 + l2] =
            make_uint2(f2tf(Wm[n * 128 + k]), f2tf(Wm[n * 128 + k + 4]));
    }
    __syncthreads();

    for (int ch = blockIdx.x; ch < nrows / 64; ch += gridDim.x) {
        int rowbase = ch * 64;
        for (int fl = tid; fl < 2048; fl += 128) {
            int l2 = fl & 31, kt = (fl >> 5) & 15, rt = fl >> 9;
            int g2 = l2 >> 2, c2 = l2 & 3;
            const float* xb = X + (size_t)(rowbase + rt * 16) * 128;
            int k = kt * 8 + c2;
            XA[(rt * 16 + kt) * 32 + l2] = make_uint4(
                f2tf(xb[g2 * 128 + k]),       f2tf(xb[(g2 + 8) * 128 + k]),
                f2tf(xb[g2 * 128 + k + 4]),   f2tf(xb[(g2 + 8) * 128 + k + 4]));
        }
        __syncthreads();

        float4 C[16];
        #pragma unroll
        for (int nt = 0; nt < 16; nt++) C[nt] = make_float4(0.f, 0.f, 0.f, 0.f);
        #pragma unroll
        for (int kt = 0; kt < 16; kt++) {
            uint4 a = XA[(w * 16 + kt) * 32 + ln];
            #pragma unroll
            for (int nt = 0; nt < 16; nt++)
                mma8(C[nt], a, WB[(kt * 16 + nt) * 32 + ln]);
        }
        int row = rowbase + w * 16 + g;
        #pragma unroll
        for (int nt = 0; nt < 16; nt++) {
            *(float2*)(OUT + (size_t)row * 128 + nt * 8 + 2 * c) = make_float2(C[nt].x, C[nt].y);
            *(float2*)(OUT + (size_t)(row + 8) * 128 + nt * 8 + 2 * c) = make_float2(C[nt].z, C[nt].w);
        }
        __syncthreads();
    }
}

// ---------- g0p: G0 = mem0.KT^T, P = rope(z).KT^T  (fp32, 2 batches/CTA) ----------
// smem floats: sKT[2][16*132] | sX[2][48*132] | cs[1024] | sn[1024]
#define GP_PITCH 132
#define GP_SKT (16 * GP_PITCH)
#define GP_SX  (48 * GP_PITCH)
#define GP_SMEM_FLOATS (2 * GP_SKT + 2 * GP_SX + 2048)
#define GP_SMEM_BYTES (GP_SMEM_FLOATS * 4)
__global__ void __launch_bounds__(128) g0p_kernel(
    const float* __restrict__ mem0,
    const float* __restrict__ zr, const float* __restrict__ zi)
{
    extern __shared__ float smp[];
    float* sKT = smp;                      // [2][16*132]
    float* sX  = smp + 2 * GP_SKT;         // [2][48*132]
    float* sCs = smp + 2 * GP_SKT + 2 * GP_SX;
    float* sSn = sCs + 1024;
    const int tid = threadIdx.x;

    for (int k = tid; k < 1024; k += 128) {
        int t = k >> 5, dm = k & 31;
        float ang = (float)t * exp2f(-0.41524101186092f * (float)dm);
        sincosf(ang, &sSn[k], &sCs[k]);
    }
    __syncthreads();

    const int bi = tid >> 6, t6 = tid & 63;
    const int uq = t6 & 3, rg = t6 >> 2;   // u tile uq*4.., rows rg, rg+16, rg+32

    for (int b0 = blockIdx.x * 2; b0 < B; b0 += gridDim.x * 2) {
        // stage mem0 rows (0..15) and KT
        for (int k = tid; k < 4096; k += 128) {
            int bj = k >> 11, idx = k & 2047, s = idx >> 7, e = idx & 127;
            sX[bj * GP_SX + s * GP_PITCH + e] = mem0[(size_t)(b0 + bj) * 2048 + idx];
            sKT[bj * GP_SKT + s * GP_PITCH + e] = g_KT[(size_t)(b0 + bj) * 2048 + idx];
        }
        // stage rope(z) rows (16..47)
        for (int k = tid; k < 4096; k += 128) {
            int bj = k >> 11, idx = k & 2047, t = idx >> 6, d = idx & 63;
            size_t zo = (size_t)((b0 + bj) * 32 + t) * 64 + d;
            float a = zr[zo], y = zi[zo];
            float cs = sCs[t * 32 + (d & 31)], sn = sSn[t * 32 + (d & 31)];
            sX[bj * GP_SX + (16 + t) * GP_PITCH + d]      = a * cs - y * sn;
            sX[bj * GP_SX + (16 + t) * GP_PITCH + 64 + d] = a * sn + y * cs;
        }
        __syncthreads();

        float acc[3][4];
        #pragma unroll
        for (int i = 0; i < 3; i++)
            #pragma unroll
            for (int jj = 0; jj < 4; jj++) acc[i][jj] = 0.f;

        const float* KTb = sKT + bi * GP_SKT;
        const float* Xb  = sX  + bi * GP_SX;
        #pragma unroll 4
        for (int e4 = 0; e4 < 32; e4++) {
            float4 kt4[4], x4[3];
            #pragma unroll
            for (int jj = 0; jj < 4; jj++)
                kt4[jj] = *(const float4*)(KTb + (uq * 4 + jj) * GP_PITCH + e4 * 4);
            #pragma unroll
            for (int i = 0; i < 3; i++)
                x4[i] = *(const float4*)(Xb + (rg + 16 * i) * GP_PITCH + e4 * 4);
            #pragma unroll
            for (int i = 0; i < 3; i++)
                #pragma unroll
                for (int jj = 0; jj < 4; jj++) {
                    acc[i][jj] = fmaf(x4[i].x, kt4[jj].x, acc[i][jj]);
                    acc[i][jj] = fmaf(x4[i].y, kt4[jj].y, acc[i][jj]);
                    acc[i][jj] = fmaf(x4[i].z, kt4[jj].z, acc[i][jj]);
                    acc[i][jj] = fmaf(x4[i].w, kt4[jj].w, acc[i][jj]);
                }
        }
        int bb = b0 + bi;
        #pragma unroll
        for (int i = 0; i < 3; i++) {
            int row = rg + 16 * i;
            #pragma unroll
            for (int jj = 0; jj < 4; jj++) {
                int u = uq * 4 + jj;
                if (row < 16) g_G0[(size_t)bb * 256 + row * 16 + u] = acc[i][jj];
                else          g_P [(size_t)bb * 512 + (row - 16) * 16 + u] = acc[i][jj];
            }
        }
        __syncthreads();
    }
}

// ---------- K1: per-batch serial chain (unchanged) ----------
__global__ void __launch_bounds__(256) k1_kernel(
    const float* __restrict__ ctrl, const float* __restrict__ ptr0,
    float* __restrict__ out)
{
    __shared__ float sG0[16][16 * 17];
    __shared__ float sAs[16][16 * 17];
    __shared__ float sP [16][512];
    __shared__ float sg [16][3][32];
    __shared__ float sbeta[16][32];
    __shared__ float scs[16][32];
    __shared__ float ssw[16][32];
    __shared__ float sb [16][16];
    __shared__ float snp[16][16];
    __shared__ float sptr[16][16];

    const int lane = threadIdx.x & 31, warp = threadIdx.x >> 5;
    const int half = lane >> 4, u = lane & 15;
    const int slot = warp * 2 + half;
    const int bb = blockIdx.x * 16 + slot;

    #pragma unroll
    for (int st = u; st < 32; st += 16) {
        int cb = (bb * 32 + st) * 3;
        float g0 = 1.0f / (1.0f + __expf(-ctrl[cb]));
        float g1 = 1.0f / (1.0f + __expf(-ctrl[cb + 1]));
        float g2 = 1.0f / (1.0f + __expf(-ctrl[cb + 2]));
        float tot = g0 + g1 + g2 + 1e-6f;
        sg[slot][0][st] = g0 / tot;
        sg[slot][1][st] = g1 / tot;
        sg[slot][2][st] = g2 / tot;
    }
    #pragma unroll
    for (int v = 0; v < 16; v++)
        sG0[slot][u * 17 + v] = g_G0[(size_t)bb * 256 + u * 16 + v];
    for (int k = u; k < 512; k += 16)
        sP[slot][k] = g_P[(size_t)bb * 512 + k];
    sptr[slot][u] = ptr0[bb * 16 + u];
    sb[slot][u] = 0.f;
    __syncwarp();
    if (u == 0) {
        float bta = 1.f;
        for (int t = 0; t < 32; t++) { bta *= (1.f - sg[slot][0][t]); sbeta[slot][t] = bta; }
        float suf = 1.f;
        for (int t = 31; t >= 0; t--) {
            scs[slot][t] = sg[slot][0][t] * suf;
            suf *= (1.f - sg[slot][0][t]);
        }
    }
    __syncwarp();

    for (int t = 0; t < 32; t++) {
        float p = sg[slot][0][t], po = sg[slot][1][t], st = sg[slot][2][t];
        float bu = sb[slot][u];
        bu = fmaf(p, sP[slot][t * 16 + u] - bu, bu);
        float np = p * sptr[slot][(u + 15) & 15] + po * sptr[slot][(u + 1) & 15]
                 + st * sptr[slot][u];
        sb[slot][u] = bu; snp[slot][u] = np;
        __syncwarp();

        float beta = sbeta[slot][t];
        float c2 = 0.125f * beta, c1 = c2 * beta;
        float l[16], mx = -1e30f;
        #pragma unroll
        for (int v = 0; v < 16; v++) {
            l[v] = fmaf(c1, sG0[slot][u * 17 + v], c2 * sb[slot][v]);
            mx = fmaxf(mx, l[v]);
        }
        float sum = 0.f;
        #pragma unroll
        for (int v = 0; v < 16; v++) { l[v] = __expf(l[v] - mx); sum += l[v]; }
        float inv = 1.0f / sum;
        #pragma unroll
        for (int v = 0; v < 16; v++) sAs[slot][u * 17 + v] = l[v] * inv;
        __syncwarp();

        float w = 0.f;
        #pragma unroll
        for (int s2 = 0; s2 < 16; s2++)
            w = fmaf(snp[slot][s2], sAs[slot][s2 * 17 + u], w);
        g_W[(size_t)bb * 512 + t * 16 + u] = w;
        sptr[slot][u] = np;
        float sw = w;
        sw += __shfl_xor_sync(0xffffffffu, sw, 8, 16);
        sw += __shfl_xor_sync(0xffffffffu, sw, 4, 16);
        sw += __shfl_xor_sync(0xffffffffu, sw, 2, 16);
        sw += __shfl_xor_sync(0xffffffffu, sw, 1, 16);
        if (u == 0) ssw[slot][t] = sw;
        __syncwarp();
    }

    for (int k = u; k < 32; k += 16) {
        g_AUX[(size_t)bb * 128 + k]      = sg[slot][0][k];
        g_AUX[(size_t)bb * 128 + 32 + k] = sbeta[slot][k];
        g_AUX[(size_t)bb * 128 + 64 + k] = scs[slot][k];
        g_AUX[(size_t)bb * 128 + 96 + k] = ssw[slot][k];
    }
    out[PTR_OFF + bb * 16 + u] = sptr[slot][u];
    unsigned m = __ballot_sync(0xffffffffu, sptr[slot][u] > 0.1f);
    if (lane == 0) atomicAdd(&g_count, __popc(m));
}

// ---------- K2: streaming output (rope replayed via rotation recurrence) ----------
__global__ void __launch_bounds__(128) k2_kernel(
    const float* __restrict__ mem0,
    const float* __restrict__ zr, const float* __restrict__ zi,
    float* __restrict__ out)
{
    const int b = blockIdx.x, j = threadIdx.x;
    __shared__ float w2[512];
    __shared__ float aux2[128];

    ((float4*)w2)[j] = ((const float4*)(g_W + (size_t)b * 512))[j];
    aux2[j] = g_AUX[(size_t)b * 128 + j];
    float V0c[16];
    #pragma unroll
    for (int s = 0; s < 16; s++) V0c[s] = g_V0[(size_t)(b * 16 + s) * 128 + j];
    __syncthreads();

    const float* pushA = aux2;
    const float* betaA = aux2 + 32;
    const float* csA   = aux2 + 64;
    const float* swA   = aux2 + 96;

    float Rv = 0.f;
    float vz = g_VZ[(size_t)(b * 32) * 128 + j];
    #pragma unroll 4
    for (int t = 0; t < 32; t++) {
        float vzn = (t < 31) ? g_VZ[(size_t)(b * 32 + t + 1) * 128 + j] : 0.f;
        Rv = fmaf(pushA[t], vz - Rv, Rv);
        float acc = 0.f;
        const float* wp = w2 + t * 16;
        #pragma unroll
        for (int u2 = 0; u2 < 16; u2++) acc = fmaf(wp[u2], V0c[u2], acc);
        out[READS_OFF + ((size_t)t * B + b) * 128 + j] = fmaf(betaA[t], acc, swA[t] * Rv);
        vz = vzn;
    }

    // rm = sum_t cS[t] * rope(z_t)[j]  via incremental rotation
    float freq = exp2f(-0.41524101186092f * (float)(j & 31));
    float sr, cr; sincosf(freq, &sr, &cr);
    float cs = 1.f, sn = 0.f;
    const float* zrp = zr + (size_t)b * 32 * 64 + (j & 63);
    const float* zip = zi + (size_t)b * 32 * 64 + (j & 63);
    float rm = 0.f;
    #pragma unroll 8
    for (int t = 0; t < 32; t++) {
        float a = zrp[t * 64], y = zip[t * 64];
        float val = (j < 64) ? (a * cs - y * sn) : (a * sn + y * cs);
        rm = fmaf(csA[t], val, rm);
        float ncs = cs * cr - sn * sr;
        sn = fmaf(sn, cr, cs * sr);
        cs = ncs;
    }
    float bf = betaA[31];
    #pragma unroll
    for (int s = 0; s < 16; s++)
        out[MEM_OFF + (size_t)(b * 16 + s) * 128 + j] =
            fmaf(bf, mem0[(size_t)(b * 16 + s) * 128 + j], rm);
}

__global__ void finalize_kernel(float* __restrict__ out) {
    out[ACT_OFF] = (float)g_count * (1.0f / (float)B);
}

extern "C" void kernel_launch(void* const* d_in, const int* in_sizes, int n_in,
                              void* d_out, int out_size) {
    const float* zr   = (const float*)d_in[0];
    const float* zi   = (const float*)d_in[1];
    const float* ctrl = (const float*)d_in[2];
    const float* mem0 = (const float*)d_in[3];
    const float* ptr0 = (const float*)d_in[4];
    const float* Wqr  = (const float*)d_in[5];
    const float* Wqi  = (const float*)d_in[6];
    const float* Wkr  = (const float*)d_in[7];
    const float* Wki  = (const float*)d_in[8];
    const float* Wvr  = (const float*)d_in[9];
    const float* Wvi  = (const float*)d_in[10];
    float* out = (float*)d_out;

    static float* d_H = nullptr;
    static float* d_Mv = nullptr;
    if (!d_H)  cudaGetSymbolAddress((void**)&d_H,  g_H);
    if (!d_Mv) cudaGetSymbolAddress((void**)&d_Mv, g_Mv);
    static float* d_KT = nullptr;
    static float* d_V0 = nullptr;
    if (!d_KT) cudaGetSymbolAddress((void**)&d_KT, g_KT);
    if (!d_V0) cudaGetSymbolAddress((void**)&d_V0, g_V0);

    cudaFuncSetAttribute(phase1z_kernel, cudaFuncAttributeMaxDynamicSharedMemorySize, Z_SMEM_BYTES);
    cudaFuncSetAttribute(gemm_kernel,    cudaFuncAttributeMaxDynamicSharedMemorySize, G_SMEM_BYTES);
    cudaFuncSetAttribute(g0p_kernel,     cudaFuncAttributeMaxDynamicSharedMemorySize, GP_SMEM_BYTES);

    hprep_kernel<<<128, 128>>>(Wqr, Wqi, Wkr, Wki, Wvr, Wvi);
    phase1z_kernel<<<296, 128, Z_SMEM_BYTES>>>(zr, zi);
    gemm_kernel<<<296, 128, G_SMEM_BYTES>>>(mem0, d_H,  d_KT, B * S);
    gemm_kernel<<<296, 128, G_SMEM_BYTES>>>(mem0, d_Mv, d_V0, B * S);
    g0p_kernel<<<444, 128, GP_SMEM_BYTES>>>(mem0, zr, zi);
    k1_kernel<<<B / 16, 256>>>(ctrl, ptr0, out);
    k2_kernel<<<B, 128>>>(mem0, zr, zi, out);
    finalize_kernel<<<1, 1>>>(out);
}

// round 14
// speedup vs baseline: 2.8528x; 1.0858x over previous
#include <cuda_runtime.h>
#include <math.h>

#define B 16384
#define T 32
#define S 16

#define READS_OFF 0
#define MEM_OFF   67108864
#define PTR_OFF   100663296
#define ACT_OFF   100925440

__device__ float g_VZ[B * T * 128];
__device__ float g_KT[B * S * 128];
__device__ float g_V0[B * S * 128];
__device__ float g_G0[B * S * S];
__device__ float g_P [B * T * S];
__device__ float g_W [B * T * S];
__device__ float g_AUX[B * 128];     // push[32], beta[32], cS[32], sw[32]
__device__ float g_H [128 * 128];
__device__ float g_Mv[128 * 128];
__device__ int   g_count;

__device__ __forceinline__ unsigned f2tf(float x) {
    unsigned r; asm("cvt.rna.tf32.f32 %0, %1;" : "=r"(r) : "f"(x)); return r;
}
__device__ __forceinline__ void mma8(float4& c, const uint4 a, const uint2 b) {
    asm("mma.sync.aligned.m16n8k8.row.col.f32.tf32.tf32.f32 "
        "{%0,%1,%2,%3}, {%4,%5,%6,%7}, {%8,%9}, {%0,%1,%2,%3};"
        : "+f"(c.x), "+f"(c.y), "+f"(c.z), "+f"(c.w)
        : "r"(a.x), "r"(a.y), "r"(a.z), "r"(a.w), "r"(b.x), "r"(b.y));
}
// M[e][a] for M = [[Wr, -Wi],[Wi, Wr]]
__device__ __forceinline__ float cmat(const float* Wr, const float* Wi, int e, int a) {
    if (e < 64) return (a < 64) ? Wr[e * 64 + a] : -Wi[e * 64 + (a - 64)];
    else        return (a < 64) ? Wi[(e - 64) * 64 + a] : Wr[(e - 64) * 64 + (a - 64)];
}

// ---------- hprep: H = Mq^T Mk, Mv expanded ----------
__global__ void hprep_kernel(const float* __restrict__ Wqr, const float* __restrict__ Wqi,
                             const float* __restrict__ Wkr, const float* __restrict__ Wki,
                             const float* __restrict__ Wvr, const float* __restrict__ Wvi) {
    int a = blockIdx.x, bb = threadIdx.x;
    float s = 0.f;
    for (int e = 0; e < 128; e++)
        s = fmaf(cmat(Wqr, Wqi, e, a), cmat(Wkr, Wki, e, bb), s);
    g_H[a * 128 + bb] = s;
    g_Mv[a * 128 + bb] = cmat(Wvr, Wvi, a, bb);
    if (a == 0 && bb == 0) g_count = 0;
}

// ---------- phase1z: VZ = rope(z) @ Mv^T  (tf32 mma) ----------
#define Z_SMEM_BYTES (32768 + 65536 + 8192)
__global__ void __launch_bounds__(128, 2) phase1z_kernel(
    const float* __restrict__ zr, const float* __restrict__ zi)
{
    extern __shared__ char smz[];
    uint4* XA  = (uint4*)smz;
    uint2* WB  = (uint2*)(smz + 32768);
    float* sCs = (float*)(smz + 98304);
    float* sSn = sCs + 1024;
    const int tid = threadIdx.x;
    const int ln = tid & 31, w = tid >> 5;
    const int g = ln >> 2, c = ln & 3;

    for (int fl = tid; fl < 8192; fl += 128) {
        int l2 = fl & 31, nt = (fl >> 5) & 15, kt = fl >> 9;
        int g2 = l2 >> 2, c2 = l2 & 3;
        int n = nt * 8 + g2, k = kt * 8 + c2;
        WB[(kt * 16 + nt) * 32 + l2] =
            make_uint2(f2tf(g_Mv[n * 128 + k]), f2tf(g_Mv[n * 128 + k + 4]));
    }
    for (int k = tid; k < 1024; k += 128) {
        int t = k >> 5, dm = k & 31;
        float ang = (float)t * exp2f(-0.41524101186092f * (float)dm);
        sincosf(ang, &sSn[k], &sCs[k]);
    }
    __syncthreads();

    for (int ch = blockIdx.x; ch < (B * T) / 64; ch += gridDim.x) {
        int rowbase = ch * 64;
        for (int fl = tid; fl < 1024; fl += 128) {
            int l2 = fl & 31, kt = (fl >> 5) & 7, rt = fl >> 8;
            int g2 = l2 >> 2, c2 = l2 & 3;
            int r1 = rt * 16 + g2, r2 = r1 + 8;
            int d1 = kt * 8 + c2, d2 = d1 + 4;
            int row1 = rowbase + r1, row2 = rowbase + r2;
            float z11 = zr[row1 * 64 + d1], y11 = zi[row1 * 64 + d1];
            float z12 = zr[row1 * 64 + d2], y12 = zi[row1 * 64 + d2];
            float z21 = zr[row2 * 64 + d1], y21 = zi[row2 * 64 + d1];
            float z22 = zr[row2 * 64 + d2], y22 = zi[row2 * 64 + d2];
            int t1 = row1 & 31, t2 = row2 & 31;
            float cA = sCs[t1 * 32 + (d1 & 31)], sA = sSn[t1 * 32 + (d1 & 31)];
            float cBv = sCs[t1 * 32 + (d2 & 31)], sB = sSn[t1 * 32 + (d2 & 31)];
            float cC = sCs[t2 * 32 + (d1 & 31)], sC = sSn[t2 * 32 + (d1 & 31)];
            float cD = sCs[t2 * 32 + (d2 & 31)], sD = sSn[t2 * 32 + (d2 & 31)];
            float xr11 = z11 * cA - y11 * sA, xi11 = z11 * sA + y11 * cA;
            float xr12 = z12 * cBv - y12 * sB, xi12 = z12 * sB + y12 * cBv;
            float xr21 = z21 * cC - y21 * sC, xi21 = z21 * sC + y21 * cC;
            float xr22 = z22 * cD - y22 * sD, xi22 = z22 * sD + y22 * cD;
            XA[(rt * 16 + kt) * 32 + l2] =
                make_uint4(f2tf(xr11), f2tf(xr21), f2tf(xr12), f2tf(xr22));
            XA[(rt * 16 + kt + 8) * 32 + l2] =
                make_uint4(f2tf(xi11), f2tf(xi21), f2tf(xi12), f2tf(xi22));
        }
        __syncthreads();

        float4 C[16];
        #pragma unroll
        for (int nt = 0; nt < 16; nt++) C[nt] = make_float4(0.f, 0.f, 0.f, 0.f);
        #pragma unroll
        for (int kt = 0; kt < 16; kt++) {
            uint4 a = XA[(w * 16 + kt) * 32 + ln];
            #pragma unroll
            for (int nt = 0; nt < 16; nt++)
                mma8(C[nt], a, WB[(kt * 16 + nt) * 32 + ln]);
        }
        int row = rowbase + w * 16 + g;
        #pragma unroll
        for (int nt = 0; nt < 16; nt++) {
            *(float2*)(g_VZ + (size_t)row * 128 + nt * 8 + 2 * c) = make_float2(C[nt].x, C[nt].y);
            *(float2*)(g_VZ + (size_t)(row + 8) * 128 + nt * 8 + 2 * c) = make_float2(C[nt].z, C[nt].w);
        }
        __syncthreads();
    }
}

// ---------- gemm2: KT = mem0 @ H^T and V0 = mem0 @ Mv^T in ONE pass ----------
// smem: XA uint4[64 rows worth] 32KB | WB uint2[2][16][16][32] 128KB = 160KB
#define G2_SMEM_BYTES (32768 + 2 * 65536)
__global__ void __launch_bounds__(256, 1) gemm2_kernel(
    const float* __restrict__ X)
{
    extern __shared__ char smg[];
    uint4* XA = (uint4*)smg;
    uint2* WB = (uint2*)(smg + 32768);
    const int tid = threadIdx.x;
    const int ln = tid & 31, w = tid >> 5;
    const int g = ln >> 2, c = ln & 3;

    for (int fl = tid; fl < 16384; fl += 256) {
        int m = fl >> 13, r = fl & 8191;
        int l2 = r & 31, nt = (r >> 5) & 15, kt = r >> 9;
        int g2 = l2 >> 2, c2 = l2 & 3;
        int n = nt * 8 + g2, k = kt * 8 + c2;
        const float* Wm = m ? g_Mv : g_H;
        WB[((m * 16 + kt) * 16 + nt) * 32 + l2] =
            make_uint2(f2tf(Wm[n * 128 + k]), f2tf(Wm[n * 128 + k + 4]));
    }
    __syncthreads();

    const int rt = w >> 1;      // row tile 0..3 (16 rows each)
    const int m  = w & 1;       // 0: KT(H), 1: V0(Mv)
    float* OUT = m ? g_V0 : g_KT;

    for (int ch = blockIdx.x; ch < (B * S) / 64; ch += gridDim.x) {
        int rowbase = ch * 64;
        for (int fl = tid; fl < 2048; fl += 256) {
            int l2 = fl & 31, kt = (fl >> 5) & 15, rt2 = fl >> 9;
            int g2 = l2 >> 2, c2 = l2 & 3;
            const float* xb = X + (size_t)(rowbase + rt2 * 16) * 128;
            int k = kt * 8 + c2;
            XA[(rt2 * 16 + kt) * 32 + l2] = make_uint4(
                f2tf(xb[g2 * 128 + k]),     f2tf(xb[(g2 + 8) * 128 + k]),
                f2tf(xb[g2 * 128 + k + 4]), f2tf(xb[(g2 + 8) * 128 + k + 4]));
        }
        __syncthreads();

        float4 C[16];
        #pragma unroll
        for (int nt = 0; nt < 16; nt++) C[nt] = make_float4(0.f, 0.f, 0.f, 0.f);
        #pragma unroll
        for (int kt = 0; kt < 16; kt++) {
            uint4 a = XA[(rt * 16 + kt) * 32 + ln];
            #pragma unroll
            for (int nt = 0; nt < 16; nt++)
                mma8(C[nt], a, WB[((m * 16 + kt) * 16 + nt) * 32 + ln]);
        }
        int row = rowbase + rt * 16 + g;
        #pragma unroll
        for (int nt = 0; nt < 16; nt++) {
            *(float2*)(OUT + (size_t)row * 128 + nt * 8 + 2 * c) = make_float2(C[nt].x, C[nt].y);
            *(float2*)(OUT + (size_t)(row + 8) * 128 + nt * 8 + 2 * c) = make_float2(C[nt].z, C[nt].w);
        }
        __syncthreads();
    }
}

// ---------- g0p: G0 = mem0.KT^T, P = rope(z).KT^T  (fp32, 2 batches/CTA) ----------
#define GP_PITCH 132
#define GP_SKT (16 * GP_PITCH)
#define GP_SX  (48 * GP_PITCH)
#define GP_SMEM_FLOATS (2 * GP_SKT + 2 * GP_SX + 2048)
#define GP_SMEM_BYTES (GP_SMEM_FLOATS * 4)
__global__ void __launch_bounds__(128) g0p_kernel(
    const float* __restrict__ mem0,
    const float* __restrict__ zr, const float* __restrict__ zi)
{
    extern __shared__ float smp[];
    float* sKT = smp;
    float* sX  = smp + 2 * GP_SKT;
    float* sCs = smp + 2 * GP_SKT + 2 * GP_SX;
    float* sSn = sCs + 1024;
    const int tid = threadIdx.x;

    for (int k = tid; k < 1024; k += 128) {
        int t = k >> 5, dm = k & 31;
        float ang = (float)t * exp2f(-0.41524101186092f * (float)dm);
        sincosf(ang, &sSn[k], &sCs[k]);
    }
    __syncthreads();

    const int bi = tid >> 6, t6 = tid & 63;
    const int uq = t6 & 3, rg = t6 >> 2;

    for (int b0 = blockIdx.x * 2; b0 < B; b0 += gridDim.x * 2) {
        for (int k = tid; k < 4096; k += 128) {
            int bj = k >> 11, idx = k & 2047, s = idx >> 7, e = idx & 127;
            sX[bj * GP_SX + s * GP_PITCH + e] = mem0[(size_t)(b0 + bj) * 2048 + idx];
            sKT[bj * GP_SKT + s * GP_PITCH + e] = g_KT[(size_t)(b0 + bj) * 2048 + idx];
        }
        for (int k = tid; k < 4096; k += 128) {
            int bj = k >> 11, idx = k & 2047, t = idx >> 6, d = idx & 63;
            size_t zo = (size_t)((b0 + bj) * 32 + t) * 64 + d;
            float a = zr[zo], y = zi[zo];
            float cs = sCs[t * 32 + (d & 31)], sn = sSn[t * 32 + (d & 31)];
            sX[bj * GP_SX + (16 + t) * GP_PITCH + d]      = a * cs - y * sn;
            sX[bj * GP_SX + (16 + t) * GP_PITCH + 64 + d] = a * sn + y * cs;
        }
        __syncthreads();

        float acc[3][4];
        #pragma unroll
        for (int i = 0; i < 3; i++)
            #pragma unroll
            for (int jj = 0; jj < 4; jj++) acc[i][jj] = 0.f;

        const float* KTb = sKT + bi * GP_SKT;
        const float* Xb  = sX  + bi * GP_SX;
        #pragma unroll 4
        for (int e4 = 0; e4 < 32; e4++) {
            float4 kt4[4], x4[3];
            #pragma unroll
            for (int jj = 0; jj < 4; jj++)
                kt4[jj] = *(const float4*)(KTb + (uq * 4 + jj) * GP_PITCH + e4 * 4);
            #pragma unroll
            for (int i = 0; i < 3; i++)
                x4[i] = *(const float4*)(Xb + (rg + 16 * i) * GP_PITCH + e4 * 4);
            #pragma unroll
            for (int i = 0; i < 3; i++)
                #pragma unroll
                for (int jj = 0; jj < 4; jj++) {
                    acc[i][jj] = fmaf(x4[i].x, kt4[jj].x, acc[i][jj]);
                    acc[i][jj] = fmaf(x4[i].y, kt4[jj].y, acc[i][jj]);
                    acc[i][jj] = fmaf(x4[i].z, kt4[jj].z, acc[i][jj]);
                    acc[i][jj] = fmaf(x4[i].w, kt4[jj].w, acc[i][jj]);
                }
        }
        int bb = b0 + bi;
        #pragma unroll
        for (int i = 0; i < 3; i++) {
            int row = rg + 16 * i;
            #pragma unroll
            for (int jj = 0; jj < 4; jj++) {
                int u = uq * 4 + jj;
                if (row < 16) g_G0[(size_t)bb * 256 + row * 16 + u] = acc[i][jj];
                else          g_P [(size_t)bb * 512 + (row - 16) * 16 + u] = acc[i][jj];
            }
        }
        __syncthreads();
    }
}

// ---------- K1: per-batch serial chain ----------
__global__ void __launch_bounds__(256) k1_kernel(
    const float* __restrict__ ctrl, const float* __restrict__ ptr0,
    float* __restrict__ out)
{
    __shared__ float sG0[16][16 * 17];
    __shared__ float sAs[16][16 * 17];
    __shared__ float sP [16][512];
    __shared__ float sg [16][3][32];
    __shared__ float sbeta[16][32];
    __shared__ float scs[16][32];
    __shared__ float ssw[16][32];
    __shared__ float sb [16][16];
    __shared__ float snp[16][16];
    __shared__ float sptr[16][16];

    const int lane = threadIdx.x & 31, warp = threadIdx.x >> 5;
    const int half = lane >> 4, u = lane & 15;
    const int slot = warp * 2 + half;
    const int bb = blockIdx.x * 16 + slot;

    #pragma unroll
    for (int st = u; st < 32; st += 16) {
        int cb = (bb * 32 + st) * 3;
        float g0 = 1.0f / (1.0f + __expf(-ctrl[cb]));
        float g1 = 1.0f / (1.0f + __expf(-ctrl[cb + 1]));
        float g2 = 1.0f / (1.0f + __expf(-ctrl[cb + 2]));
        float tot = g0 + g1 + g2 + 1e-6f;
        sg[slot][0][st] = g0 / tot;
        sg[slot][1][st] = g1 / tot;
        sg[slot][2][st] = g2 / tot;
    }
    #pragma unroll
    for (int v = 0; v < 16; v++)
        sG0[slot][u * 17 + v] = g_G0[(size_t)bb * 256 + u * 16 + v];
    for (int k = u; k < 512; k += 16)
        sP[slot][k] = g_P[(size_t)bb * 512 + k];
    sptr[slot][u] = ptr0[bb * 16 + u];
    sb[slot][u] = 0.f;
    __syncwarp();
    if (u == 0) {
        float bta = 1.f;
        for (int t = 0; t < 32; t++) { bta *= (1.f - sg[slot][0][t]); sbeta[slot][t] = bta; }
        float suf = 1.f;
        for (int t = 31; t >= 0; t--) {
            scs[slot][t] = sg[slot][0][t] * suf;
            suf *= (1.f - sg[slot][0][t]);
        }
    }
    __syncwarp();

    for (int t = 0; t < 32; t++) {
        float p = sg[slot][0][t], po = sg[slot][1][t], st = sg[slot][2][t];
        float bu = sb[slot][u];
        bu = fmaf(p, sP[slot][t * 16 + u] - bu, bu);
        float np = p * sptr[slot][(u + 15) & 15] + po * sptr[slot][(u + 1) & 15]
                 + st * sptr[slot][u];
        sb[slot][u] = bu; snp[slot][u] = np;
        __syncwarp();

        float beta = sbeta[slot][t];
        float c2 = 0.125f * beta, c1 = c2 * beta;
        float l[16], mx = -1e30f;
        #pragma unroll
        for (int v = 0; v < 16; v++) {
            l[v] = fmaf(c1, sG0[slot][u * 17 + v], c2 * sb[slot][v]);
            mx = fmaxf(mx, l[v]);
        }
        float sum = 0.f;
        #pragma unroll
        for (int v = 0; v < 16; v++) { l[v] = __expf(l[v] - mx); sum += l[v]; }
        float inv = 1.0f / sum;
        #pragma unroll
        for (int v = 0; v < 16; v++) sAs[slot][u * 17 + v] = l[v] * inv;
        __syncwarp();

        float w = 0.f;
        #pragma unroll
        for (int s2 = 0; s2 < 16; s2++)
            w = fmaf(snp[slot][s2], sAs[slot][s2 * 17 + u], w);
        g_W[(size_t)bb * 512 + t * 16 + u] = w;
        sptr[slot][u] = np;
        float sw = w;
        sw += __shfl_xor_sync(0xffffffffu, sw, 8, 16);
        sw += __shfl_xor_sync(0xffffffffu, sw, 4, 16);
        sw += __shfl_xor_sync(0xffffffffu, sw, 2, 16);
        sw += __shfl_xor_sync(0xffffffffu, sw, 1, 16);
        if (u == 0) ssw[slot][t] = sw;
        __syncwarp();
    }

    for (int k = u; k < 32; k += 16) {
        g_AUX[(size_t)bb * 128 + k]      = sg[slot][0][k];
        g_AUX[(size_t)bb * 128 + 32 + k] = sbeta[slot][k];
        g_AUX[(size_t)bb * 128 + 64 + k] = scs[slot][k];
        g_AUX[(size_t)bb * 128 + 96 + k] = ssw[slot][k];
    }
    out[PTR_OFF + bb * 16 + u] = sptr[slot][u];
    unsigned m = __ballot_sync(0xffffffffu, sptr[slot][u] > 0.1f);
    if (lane == 0) atomicAdd(&g_count, __popc(m));
}

// ---------- K2: streaming output ----------
__global__ void __launch_bounds__(128) k2_kernel(
    const float* __restrict__ mem0,
    const float* __restrict__ zr, const float* __restrict__ zi,
    float* __restrict__ out)
{
    const int b = blockIdx.x, j = threadIdx.x;
    __shared__ float w2[512];
    __shared__ float aux2[128];

    ((float4*)w2)[j] = ((const float4*)(g_W + (size_t)b * 512))[j];
    aux2[j] = g_AUX[(size_t)b * 128 + j];
    float V0c[16];
    #pragma unroll
    for (int s = 0; s < 16; s++) V0c[s] = g_V0[(size_t)(b * 16 + s) * 128 + j];
    __syncthreads();

    const float* pushA = aux2;
    const float* betaA = aux2 + 32;
    const float* csA   = aux2 + 64;
    const float* swA   = aux2 + 96;

    float Rv = 0.f;
    float vz = g_VZ[(size_t)(b * 32) * 128 + j];
    #pragma unroll 4
    for (int t = 0; t < 32; t++) {
        float vzn = (t < 31) ? g_VZ[(size_t)(b * 32 + t + 1) * 128 + j] : 0.f;
        Rv = fmaf(pushA[t], vz - Rv, Rv);
        float acc = 0.f;
        const float* wp = w2 + t * 16;
        #pragma unroll
        for (int u2 = 0; u2 < 16; u2++) acc = fmaf(wp[u2], V0c[u2], acc);
        out[READS_OFF + ((size_t)t * B + b) * 128 + j] = fmaf(betaA[t], acc, swA[t] * Rv);
        vz = vzn;
    }

    float freq = exp2f(-0.41524101186092f * (float)(j & 31));
    float sr, cr; sincosf(freq, &sr, &cr);
    float cs = 1.f, sn = 0.f;
    const float* zrp = zr + (size_t)b * 32 * 64 + (j & 63);
    const float* zip = zi + (size_t)b * 32 * 64 + (j & 63);
    float rm = 0.f;
    #pragma unroll 8
    for (int t = 0; t < 32; t++) {
        float a = zrp[t * 64], y = zip[t * 64];
        float val = (j < 64) ? (a * cs - y * sn) : (a * sn + y * cs);
        rm = fmaf(csA[t], val, rm);
        float ncs = cs * cr - sn * sr;
        sn = fmaf(sn, cr, cs * sr);
        cs = ncs;
    }
    float bf = betaA[31];
    #pragma unroll
    for (int s = 0; s < 16; s++)
        out[MEM_OFF + (size_t)(b * 16 + s) * 128 + j] =
            fmaf(bf, mem0[(size_t)(b * 16 + s) * 128 + j], rm);
}

__global__ void finalize_kernel(float* __restrict__ out) {
    out[ACT_OFF] = (float)g_count * (1.0f / (float)B);
}

extern "C" void kernel_launch(void* const* d_in, const int* in_sizes, int n_in,
                              void* d_out, int out_size) {
    const float* zr   = (const float*)d_in[0];
    const float* zi   = (const float*)d_in[1];
    const float* ctrl = (const float*)d_in[2];
    const float* mem0 = (const float*)d_in[3];
    const float* ptr0 = (const float*)d_in[4];
    const float* Wqr  = (const float*)d_in[5];
    const float* Wqi  = (const float*)d_in[6];
    const float* Wkr  = (const float*)d_in[7];
    const float* Wki  = (const float*)d_in[8];
    const float* Wvr  = (const float*)d_in[9];
    const float* Wvi  = (const float*)d_in[10];
    float* out = (float*)d_out;

    cudaFuncSetAttribute(phase1z_kernel, cudaFuncAttributeMaxDynamicSharedMemorySize, Z_SMEM_BYTES);
    cudaFuncSetAttribute(gemm2_kernel,   cudaFuncAttributeMaxDynamicSharedMemorySize, G2_SMEM_BYTES);
    cudaFuncSetAttribute(g0p_kernel,     cudaFuncAttributeMaxDynamicSharedMemorySize, GP_SMEM_BYTES);

    hprep_kernel<<<128, 128>>>(Wqr, Wqi, Wkr, Wki, Wvr, Wvi);
    phase1z_kernel<<<296, 128, Z_SMEM_BYTES>>>(zr, zi);
    gemm2_kernel<<<148, 256, G2_SMEM_BYTES>>>(mem0);
    g0p_kernel<<<444, 128, GP_SMEM_BYTES>>>(mem0, zr, zi);
    k1_kernel<<<B / 16, 256>>>(ctrl, ptr0, out);
    k2_kernel<<<B, 128>>>(mem0, zr, zi, out);
    finalize_kernel<<<1, 1>>>(out);
}

// round 15
// speedup vs baseline: 2.9920x; 1.0488x over previous
#include <cuda_runtime.h>
#include <math.h>

#define B 16384
#define T 32
#define S 16

#define READS_OFF 0
#define MEM_OFF   67108864
#define PTR_OFF   100663296
#define ACT_OFF   100925440

__device__ float g_VZ[B * T * 128];
__device__ float g_KT[B * S * 128];
__device__ float g_V0[B * S * 128];
__device__ float g_G0[B * S * S];
__device__ float g_P [B * T * S];
__device__ float g_W [B * T * S];
__device__ float g_AUX[B * 128];     // push[32], beta[32], cS[32], sw[32]
__device__ float g_H [128 * 128];
__device__ float g_Mv[128 * 128];
__device__ int   g_count;

__device__ __forceinline__ unsigned f2tf(float x) {
    unsigned r; asm("cvt.rna.tf32.f32 %0, %1;" : "=r"(r) : "f"(x)); return r;
}
__device__ __forceinline__ void mma8(float4& c, const uint4 a, const uint2 b) {
    asm("mma.sync.aligned.m16n8k8.row.col.f32.tf32.tf32.f32 "
        "{%0,%1,%2,%3}, {%4,%5,%6,%7}, {%8,%9}, {%0,%1,%2,%3};"
        : "+f"(c.x), "+f"(c.y), "+f"(c.z), "+f"(c.w)
        : "r"(a.x), "r"(a.y), "r"(a.z), "r"(a.w), "r"(b.x), "r"(b.y));
}
// M[e][a] for M = [[Wr, -Wi],[Wi, Wr]]
__device__ __forceinline__ float cmat(const float* Wr, const float* Wi, int e, int a) {
    if (e < 64) return (a < 64) ? Wr[e * 64 + a] : -Wi[e * 64 + (a - 64)];
    else        return (a < 64) ? Wi[(e - 64) * 64 + a] : Wr[(e - 64) * 64 + (a - 64)];
}

// ---------- hprep: H = Mq^T Mk, Mv expanded ----------
__global__ void hprep_kernel(const float* __restrict__ Wqr, const float* __restrict__ Wqi,
                             const float* __restrict__ Wkr, const float* __restrict__ Wki,
                             const float* __restrict__ Wvr, const float* __restrict__ Wvi) {
    int a = blockIdx.x, bb = threadIdx.x;
    float s = 0.f;
    for (int e = 0; e < 128; e++)
        s = fmaf(cmat(Wqr, Wqi, e, a), cmat(Wkr, Wki, e, bb), s);
    g_H[a * 128 + bb] = s;
    g_Mv[a * 128 + bb] = cmat(Wvr, Wvi, a, bb);
    if (a == 0 && bb == 0) g_count = 0;
}

// ---------- phase1z: VZ = rope(z) @ Mv^T  (tf32 mma) ----------
#define Z_SMEM_BYTES (32768 + 65536 + 8192)
__global__ void __launch_bounds__(128, 2) phase1z_kernel(
    const float* __restrict__ zr, const float* __restrict__ zi)
{
    extern __shared__ char smz[];
    uint4* XA  = (uint4*)smz;
    uint2* WB  = (uint2*)(smz + 32768);
    float* sCs = (float*)(smz + 98304);
    float* sSn = sCs + 1024;
    const int tid = threadIdx.x;
    const int ln = tid & 31, w = tid >> 5;
    const int g = ln >> 2, c = ln & 3;

    for (int fl = tid; fl < 8192; fl += 128) {
        int l2 = fl & 31, nt = (fl >> 5) & 15, kt = fl >> 9;
        int g2 = l2 >> 2, c2 = l2 & 3;
        int n = nt * 8 + g2, k = kt * 8 + c2;
        WB[(kt * 16 + nt) * 32 + l2] =
            make_uint2(f2tf(g_Mv[n * 128 + k]), f2tf(g_Mv[n * 128 + k + 4]));
    }
    for (int k = tid; k < 1024; k += 128) {
        int t = k >> 5, dm = k & 31;
        float ang = (float)t * exp2f(-0.41524101186092f * (float)dm);
        sincosf(ang, &sSn[k], &sCs[k]);
    }
    __syncthreads();

    for (int ch = blockIdx.x; ch < (B * T) / 64; ch += gridDim.x) {
        int rowbase = ch * 64;
        for (int fl = tid; fl < 1024; fl += 128) {
            int l2 = fl & 31, kt = (fl >> 5) & 7, rt = fl >> 8;
            int g2 = l2 >> 2, c2 = l2 & 3;
            int r1 = rt * 16 + g2, r2 = r1 + 8;
            int d1 = kt * 8 + c2, d2 = d1 + 4;
            int row1 = rowbase + r1, row2 = rowbase + r2;
            float z11 = zr[row1 * 64 + d1], y11 = zi[row1 * 64 + d1];
            float z12 = zr[row1 * 64 + d2], y12 = zi[row1 * 64 + d2];
            float z21 = zr[row2 * 64 + d1], y21 = zi[row2 * 64 + d1];
            float z22 = zr[row2 * 64 + d2], y22 = zi[row2 * 64 + d2];
            int t1 = row1 & 31, t2 = row2 & 31;
            float cA = sCs[t1 * 32 + (d1 & 31)], sA = sSn[t1 * 32 + (d1 & 31)];
            float cBv = sCs[t1 * 32 + (d2 & 31)], sB = sSn[t1 * 32 + (d2 & 31)];
            float cC = sCs[t2 * 32 + (d1 & 31)], sC = sSn[t2 * 32 + (d1 & 31)];
            float cD = sCs[t2 * 32 + (d2 & 31)], sD = sSn[t2 * 32 + (d2 & 31)];
            float xr11 = z11 * cA - y11 * sA, xi11 = z11 * sA + y11 * cA;
            float xr12 = z12 * cBv - y12 * sB, xi12 = z12 * sB + y12 * cBv;
            float xr21 = z21 * cC - y21 * sC, xi21 = z21 * sC + y21 * cC;
            float xr22 = z22 * cD - y22 * sD, xi22 = z22 * sD + y22 * cD;
            XA[(rt * 16 + kt) * 32 + l2] =
                make_uint4(f2tf(xr11), f2tf(xr21), f2tf(xr12), f2tf(xr22));
            XA[(rt * 16 + kt + 8) * 32 + l2] =
                make_uint4(f2tf(xi11), f2tf(xi21), f2tf(xi12), f2tf(xi22));
        }
        __syncthreads();

        float4 C[16];
        #pragma unroll
        for (int nt = 0; nt < 16; nt++) C[nt] = make_float4(0.f, 0.f, 0.f, 0.f);
        #pragma unroll
        for (int kt = 0; kt < 16; kt++) {
            uint4 a = XA[(w * 16 + kt) * 32 + ln];
            #pragma unroll
            for (int nt = 0; nt < 16; nt++)
                mma8(C[nt], a, WB[(kt * 16 + nt) * 32 + ln]);
        }
        int row = rowbase + w * 16 + g;
        #pragma unroll
        for (int nt = 0; nt < 16; nt++) {
            *(float2*)(g_VZ + (size_t)row * 128 + nt * 8 + 2 * c) = make_float2(C[nt].x, C[nt].y);
            *(float2*)(g_VZ + (size_t)(row + 8) * 128 + nt * 8 + 2 * c) = make_float2(C[nt].z, C[nt].w);
        }
        __syncthreads();
    }
}

// ---------- gemm2: KT = mem0 @ H^T and V0 = mem0 @ Mv^T in ONE pass ----------
#define G2_SMEM_BYTES (32768 + 2 * 65536)
__global__ void __launch_bounds__(256, 1) gemm2_kernel(
    const float* __restrict__ X)
{
    extern __shared__ char smg[];
    uint4* XA = (uint4*)smg;
    uint2* WB = (uint2*)(smg + 32768);
    const int tid = threadIdx.x;
    const int ln = tid & 31, w = tid >> 5;
    const int g = ln >> 2, c = ln & 3;

    for (int fl = tid; fl < 16384; fl += 256) {
        int m = fl >> 13, r = fl & 8191;
        int l2 = r & 31, nt = (r >> 5) & 15, kt = r >> 9;
        int g2 = l2 >> 2, c2 = l2 & 3;
        int n = nt * 8 + g2, k = kt * 8 + c2;
        const float* Wm = m ? g_Mv : g_H;
        WB[((m * 16 + kt) * 16 + nt) * 32 + l2] =
            make_uint2(f2tf(Wm[n * 128 + k]), f2tf(Wm[n * 128 + k + 4]));
    }
    __syncthreads();

    const int rt = w >> 1;
    const int m  = w & 1;
    float* OUT = m ? g_V0 : g_KT;

    for (int ch = blockIdx.x; ch < (B * S) / 64; ch += gridDim.x) {
        int rowbase = ch * 64;
        for (int fl = tid; fl < 2048; fl += 256) {
            int l2 = fl & 31, kt = (fl >> 5) & 15, rt2 = fl >> 9;
            int g2 = l2 >> 2, c2 = l2 & 3;
            const float* xb = X + (size_t)(rowbase + rt2 * 16) * 128;
            int k = kt * 8 + c2;
            XA[(rt2 * 16 + kt) * 32 + l2] = make_uint4(
                f2tf(xb[g2 * 128 + k]),     f2tf(xb[(g2 + 8) * 128 + k]),
                f2tf(xb[g2 * 128 + k + 4]), f2tf(xb[(g2 + 8) * 128 + k + 4]));
        }
        __syncthreads();

        float4 C[16];
        #pragma unroll
        for (int nt = 0; nt < 16; nt++) C[nt] = make_float4(0.f, 0.f, 0.f, 0.f);
        #pragma unroll
        for (int kt = 0; kt < 16; kt++) {
            uint4 a = XA[(rt * 16 + kt) * 32 + ln];
            #pragma unroll
            for (int nt = 0; nt < 16; nt++)
                mma8(C[nt], a, WB[((m * 16 + kt) * 16 + nt) * 32 + ln]);
        }
        int row = rowbase + rt * 16 + g;
        #pragma unroll
        for (int nt = 0; nt < 16; nt++) {
            *(float2*)(OUT + (size_t)row * 128 + nt * 8 + 2 * c) = make_float2(C[nt].x, C[nt].y);
            *(float2*)(OUT + (size_t)(row + 8) * 128 + nt * 8 + 2 * c) = make_float2(C[nt].z, C[nt].w);
        }
        __syncthreads();
    }
}

// ---------- g0p v2: 256 thr, 2 batches/CTA, conflict-free tiling ----------
#define GP_PITCH 132
#define GP_SKT (16 * GP_PITCH)
#define GP_SX  (48 * GP_PITCH)
#define GP_SMEM_FLOATS (2 * GP_SKT + 2 * GP_SX + 2048)
#define GP_SMEM_BYTES (GP_SMEM_FLOATS * 4)
__global__ void __launch_bounds__(256) g0p_kernel(
    const float* __restrict__ mem0,
    const float* __restrict__ zr, const float* __restrict__ zi)
{
    extern __shared__ float smp[];
    float* sKT = smp;
    float* sX  = smp + 2 * GP_SKT;
    float* sCs = smp + 2 * GP_SKT + 2 * GP_SX;
    float* sSn = sCs + 1024;
    const int tid = threadIdx.x;

    for (int k = tid; k < 1024; k += 256) {
        int t = k >> 5, dm = k & 31;
        float ang = (float)t * exp2f(-0.41524101186092f * (float)dm);
        sincosf(ang, &sSn[k], &sCs[k]);
    }
    __syncthreads();

    const int bi = tid >> 7, t7 = tid & 127;
    const int uq = t7 & 7;          // cols uq, uq+8
    const int rg = t7 >> 3;         // rows rg, rg+16, rg+32

    for (int b0 = blockIdx.x * 2; b0 < B; b0 += gridDim.x * 2) {
        for (int k = tid; k < 4096; k += 256) {
            int bj = k >> 11, idx = k & 2047, s = idx >> 7, e = idx & 127;
            sX[bj * GP_SX + s * GP_PITCH + e] = mem0[(size_t)(b0 + bj) * 2048 + idx];
            sKT[bj * GP_SKT + s * GP_PITCH + e] = g_KT[(size_t)(b0 + bj) * 2048 + idx];
        }
        for (int k = tid; k < 4096; k += 256) {
            int bj = k >> 11, idx = k & 2047, t = idx >> 6, d = idx & 63;
            size_t zo = (size_t)((b0 + bj) * 32 + t) * 64 + d;
            float a = zr[zo], y = zi[zo];
            float cs = sCs[t * 32 + (d & 31)], sn = sSn[t * 32 + (d & 31)];
            sX[bj * GP_SX + (16 + t) * GP_PITCH + d]      = a * cs - y * sn;
            sX[bj * GP_SX + (16 + t) * GP_PITCH + 64 + d] = a * sn + y * cs;
        }
        __syncthreads();

        float acc[3][2];
        #pragma unroll
        for (int i = 0; i < 3; i++) { acc[i][0] = 0.f; acc[i][1] = 0.f; }

        const float* KTb = sKT + bi * GP_SKT;
        const float* Xb  = sX  + bi * GP_SX;
        #pragma unroll 4
        for (int e4 = 0; e4 < 32; e4++) {
            float4 kt4[2], x4[3];
            #pragma unroll
            for (int jj = 0; jj < 2; jj++)
                kt4[jj] = *(const float4*)(KTb + (uq + jj * 8) * GP_PITCH + e4 * 4);
            #pragma unroll
            for (int i = 0; i < 3; i++)
                x4[i] = *(const float4*)(Xb + (rg + 16 * i) * GP_PITCH + e4 * 4);
            #pragma unroll
            for (int i = 0; i < 3; i++)
                #pragma unroll
                for (int jj = 0; jj < 2; jj++) {
                    acc[i][jj] = fmaf(x4[i].x, kt4[jj].x, acc[i][jj]);
                    acc[i][jj] = fmaf(x4[i].y, kt4[jj].y, acc[i][jj]);
                    acc[i][jj] = fmaf(x4[i].z, kt4[jj].z, acc[i][jj]);
                    acc[i][jj] = fmaf(x4[i].w, kt4[jj].w, acc[i][jj]);
                }
        }
        int bb = b0 + bi;
        #pragma unroll
        for (int i = 0; i < 3; i++) {
            int row = rg + 16 * i;
            #pragma unroll
            for (int jj = 0; jj < 2; jj++) {
                int u = uq + jj * 8;
                if (row < 16) g_G0[(size_t)bb * 256 + row * 16 + u] = acc[i][jj];
                else          g_P [(size_t)bb * 512 + (row - 16) * 16 + u] = acc[i][jj];
            }
        }
        __syncthreads();
    }
}

// ---------- K1: per-batch serial chain ----------
__global__ void __launch_bounds__(256) k1_kernel(
    const float* __restrict__ ctrl, const float* __restrict__ ptr0,
    float* __restrict__ out)
{
    __shared__ float sG0[16][16 * 17];
    __shared__ float sAs[16][16 * 17];
    __shared__ float sP [16][512];
    __shared__ float sg [16][3][32];
    __shared__ float sbeta[16][32];
    __shared__ float scs[16][32];
    __shared__ float ssw[16][32];
    __shared__ float sb [16][16];
    __shared__ float snp[16][16];
    __shared__ float sptr[16][16];

    const int lane = threadIdx.x & 31, warp = threadIdx.x >> 5;
    const int half = lane >> 4, u = lane & 15;
    const int slot = warp * 2 + half;
    const int bb = blockIdx.x * 16 + slot;

    #pragma unroll
    for (int st = u; st < 32; st += 16) {
        int cb = (bb * 32 + st) * 3;
        float g0 = 1.0f / (1.0f + __expf(-ctrl[cb]));
        float g1 = 1.0f / (1.0f + __expf(-ctrl[cb + 1]));
        float g2 = 1.0f / (1.0f + __expf(-ctrl[cb + 2]));
        float tot = g0 + g1 + g2 + 1e-6f;
        sg[slot][0][st] = g0 / tot;
        sg[slot][1][st] = g1 / tot;
        sg[slot][2][st] = g2 / tot;
    }
    #pragma unroll
    for (int v = 0; v < 16; v++)
        sG0[slot][u * 17 + v] = g_G0[(size_t)bb * 256 + u * 16 + v];
    for (int k = u; k < 512; k += 16)
        sP[slot][k] = g_P[(size_t)bb * 512 + k];
    sptr[slot][u] = ptr0[bb * 16 + u];
    sb[slot][u] = 0.f;
    __syncwarp();
    if (u == 0) {
        float bta = 1.f;
        for (int t = 0; t < 32; t++) { bta *= (1.f - sg[slot][0][t]); sbeta[slot][t] = bta; }
        float suf = 1.f;
        for (int t = 31; t >= 0; t--) {
            scs[slot][t] = sg[slot][0][t] * suf;
            suf *= (1.f - sg[slot][0][t]);
        }
    }
    __syncwarp();

    for (int t = 0; t < 32; t++) {
        float p = sg[slot][0][t], po = sg[slot][1][t], st = sg[slot][2][t];
        float bu = sb[slot][u];
        bu = fmaf(p, sP[slot][t * 16 + u] - bu, bu);
        float np = p * sptr[slot][(u + 15) & 15] + po * sptr[slot][(u + 1) & 15]
                 + st * sptr[slot][u];
        sb[slot][u] = bu; snp[slot][u] = np;
        __syncwarp();

        float beta = sbeta[slot][t];
        float c2 = 0.125f * beta, c1 = c2 * beta;
        float l[16], mx = -1e30f;
        #pragma unroll
        for (int v = 0; v < 16; v++) {
            l[v] = fmaf(c1, sG0[slot][u * 17 + v], c2 * sb[slot][v]);
            mx = fmaxf(mx, l[v]);
        }
        float sum = 0.f;
        #pragma unroll
        for (int v = 0; v < 16; v++) { l[v] = __expf(l[v] - mx); sum += l[v]; }
        float inv = 1.0f / sum;
        #pragma unroll
        for (int v = 0; v < 16; v++) sAs[slot][u * 17 + v] = l[v] * inv;
        __syncwarp();

        float w = 0.f;
        #pragma unroll
        for (int s2 = 0; s2 < 16; s2++)
            w = fmaf(snp[slot][s2], sAs[slot][s2 * 17 + u], w);
        g_W[(size_t)bb * 512 + t * 16 + u] = w;
        sptr[slot][u] = np;
        float sw = w;
        sw += __shfl_xor_sync(0xffffffffu, sw, 8, 16);
        sw += __shfl_xor_sync(0xffffffffu, sw, 4, 16);
        sw += __shfl_xor_sync(0xffffffffu, sw, 2, 16);
        sw += __shfl_xor_sync(0xffffffffu, sw, 1, 16);
        if (u == 0) ssw[slot][t] = sw;
        __syncwarp();
    }

    for (int k = u; k < 32; k += 16) {
        g_AUX[(size_t)bb * 128 + k]      = sg[slot][0][k];
        g_AUX[(size_t)bb * 128 + 32 + k] = sbeta[slot][k];
        g_AUX[(size_t)bb * 128 + 64 + k] = scs[slot][k];
        g_AUX[(size_t)bb * 128 + 96 + k] = ssw[slot][k];
    }
    out[PTR_OFF + bb * 16 + u] = sptr[slot][u];
    unsigned m = __ballot_sync(0xffffffffu, sptr[slot][u] > 0.1f);
    if (lane == 0) atomicAdd(&g_count, __popc(m));
}

// ---------- K2: streaming output ----------
__global__ void __launch_bounds__(128) k2_kernel(
    const float* __restrict__ mem0,
    const float* __restrict__ zr, const float* __restrict__ zi,
    float* __restrict__ out)
{
    const int b = blockIdx.x, j = threadIdx.x;
    __shared__ float w2[512];
    __shared__ float aux2[128];

    ((float4*)w2)[j] = ((const float4*)(g_W + (size_t)b * 512))[j];
    aux2[j] = g_AUX[(size_t)b * 128 + j];
    float V0c[16];
    #pragma unroll
    for (int s = 0; s < 16; s++) V0c[s] = g_V0[(size_t)(b * 16 + s) * 128 + j];
    __syncthreads();

    const float* pushA = aux2;
    const float* betaA = aux2 + 32;
    const float* csA   = aux2 + 64;
    const float* swA   = aux2 + 96;

    float Rv = 0.f;
    float vz = g_VZ[(size_t)(b * 32) * 128 + j];
    #pragma unroll 4
    for (int t = 0; t < 32; t++) {
        float vzn = (t < 31) ? g_VZ[(size_t)(b * 32 + t + 1) * 128 + j] : 0.f;
        Rv = fmaf(pushA[t], vz - Rv, Rv);
        float acc = 0.f;
        const float* wp = w2 + t * 16;
        #pragma unroll
        for (int u2 = 0; u2 < 16; u2++) acc = fmaf(wp[u2], V0c[u2], acc);
        out[READS_OFF + ((size_t)t * B + b) * 128 + j] = fmaf(betaA[t], acc, swA[t] * Rv);
        vz = vzn;
    }

    float freq = exp2f(-0.41524101186092f * (float)(j & 31));
    float sr, cr; sincosf(freq, &sr, &cr);
    float cs = 1.f, sn = 0.f;
    const float* zrp = zr + (size_t)b * 32 * 64 + (j & 63);
    const float* zip = zi + (size_t)b * 32 * 64 + (j & 63);
    float rm = 0.f;
    #pragma unroll 8
    for (int t = 0; t < 32; t++) {
        float a = zrp[t * 64], y = zip[t * 64];
        float val = (j < 64) ? (a * cs - y * sn) : (a * sn + y * cs);
        rm = fmaf(csA[t], val, rm);
        float ncs = cs * cr - sn * sr;
        sn = fmaf(sn, cr, cs * sr);
        cs = ncs;
    }
    float bf = betaA[31];
    #pragma unroll
    for (int s = 0; s < 16; s++)
        out[MEM_OFF + (size_t)(b * 16 + s) * 128 + j] =
            fmaf(bf, mem0[(size_t)(b * 16 + s) * 128 + j], rm);
}

__global__ void finalize_kernel(float* __restrict__ out) {
    out[ACT_OFF] = (float)g_count * (1.0f / (float)B);
}

extern "C" void kernel_launch(void* const* d_in, const int* in_sizes, int n_in,
                              void* d_out, int out_size) {
    const float* zr   = (const float*)d_in[0];
    const float* zi   = (const float*)d_in[1];
    const float* ctrl = (const float*)d_in[2];
    const float* mem0 = (const float*)d_in[3];
    const float* ptr0 = (const float*)d_in[4];
    const float* Wqr  = (const float*)d_in[5];
    const float* Wqi  = (const float*)d_in[6];
    const float* Wkr  = (const float*)d_in[7];
    const float* Wki  = (const float*)d_in[8];
    const float* Wvr  = (const float*)d_in[9];
    const float* Wvi  = (const float*)d_in[10];
    float* out = (float*)d_out;

    cudaFuncSetAttribute(phase1z_kernel, cudaFuncAttributeMaxDynamicSharedMemorySize, Z_SMEM_BYTES);
    cudaFuncSetAttribute(gemm2_kernel,   cudaFuncAttributeMaxDynamicSharedMemorySize, G2_SMEM_BYTES);
    cudaFuncSetAttribute(g0p_kernel,     cudaFuncAttributeMaxDynamicSharedMemorySize, GP_SMEM_BYTES);

    hprep_kernel<<<128, 128>>>(Wqr, Wqi, Wkr, Wki, Wvr, Wvi);
    phase1z_kernel<<<296, 128, Z_SMEM_BYTES>>>(zr, zi);
    gemm2_kernel<<<148, 256, G2_SMEM_BYTES>>>(mem0);
    g0p_kernel<<<444, 256, GP_SMEM_BYTES>>>(mem0, zr, zi);
    k1_kernel<<<B / 16, 256>>>(ctrl, ptr0, out);
    k2_kernel<<<B, 128>>>(mem0, zr, zi, out);
    finalize_kernel<<<1, 1>>>(out);
}